// round 11
// baseline (speedup 1.0000x reference)
#include <cuda_runtime.h>
#include <cuda_bf16.h>
#include <cstdint>
#include <math.h>

#define BB 8192
#define DD 1024
#define EE 8
#define NQv 8
#define NLv 2
#define HHv 1024

// ---------------- scratch (static device globals: no allocation) ----------------
__device__ float g_X1[(size_t)BB * DD];                 // inter-block activations
__device__ uint2 g_Hpk[(size_t)BB * 2 * (HHv / 2)];     // hidden packed {hi-pair, lo-pair}
__device__ uint2 g_zpk[HHv / 2];                        // permanent zero page
__device__ float g_Eout[(size_t)BB * 2 * DD];           // per-slot GEMM output
__device__ __nv_bfloat16 g_w2Thi[(size_t)2 * EE * DD * HHv]; // w2^T [e][n][k] hi
__device__ __nv_bfloat16 g_w2Tlo[(size_t)2 * EE * DD * HHv]; // w2^T [e][n][k] lo
__device__ int   g_cnt[EE];
__device__ int   g_list[EE * BB];                       // entries encode row*2+slot
__device__ int2   g_sel[BB];                            // per-row selected experts
__device__ float2 g_wgt[BB];                            // per-row gate weights

// ---------------- generic PTX helpers ----------------
static __device__ __forceinline__ uint32_t smem_u32(const void* p) {
    uint32_t a;
    asm("{ .reg .u64 t; cvta.to.shared.u64 t, %1; cvt.u32.u64 %0, t; }" : "=r"(a) : "l"(p));
    return a;
}
static __device__ __forceinline__ void cp16(uint32_t dst, const void* src) {
    asm volatile("cp.async.cg.shared.global [%0], [%1], 16;" :: "r"(dst), "l"(src) : "memory");
}
static __device__ __forceinline__ void cp_commit() {
    asm volatile("cp.async.commit_group;" ::: "memory");
}
static __device__ __forceinline__ void ldm4(uint32_t* r, uint32_t addr) {
    asm volatile("ldmatrix.sync.aligned.m8n8.x4.shared.b16 {%0,%1,%2,%3}, [%4];"
        : "=r"(r[0]), "=r"(r[1]), "=r"(r[2]), "=r"(r[3]) : "r"(addr));
}
static __device__ __forceinline__ void mma16816(float* c, const uint32_t* a, const uint32_t* b) {
    asm volatile("mma.sync.aligned.m16n8k16.row.col.f32.bf16.bf16.f32 "
        "{%0,%1,%2,%3}, {%4,%5,%6,%7}, {%8,%9}, {%0,%1,%2,%3};"
        : "+f"(c[0]), "+f"(c[1]), "+f"(c[2]), "+f"(c[3])
        : "r"(a[0]), "r"(a[1]), "r"(a[2]), "r"(a[3]), "r"(b[0]), "r"(b[1]));
}

// ---------------- GEMM tile config (B-only 4-stage smem ring, A via LDG) ----------------
#define BM 128
#define BN 128
#define BK 32
#define NCH (HHv / BK)                 // 32
#define RSTR 80                         // bytes per SMEM row (16B-aligned, conflict-free)
#define TILE_BYT (BM * RSTR)            // 10240
#define BSTG_BYT (2 * TILE_BYT)         // Bhi + Blo per stage = 20480
#define NSTAGE 4
#define GEMM_SMEM (NSTAGE * BSTG_BYT)   // 81920

// ---------------- w2 -> w2^T, split fp32 into bf16 hi/lo ----------------
__global__ __launch_bounds__(256) void k_w2t(const float* __restrict__ w2)
{
    __shared__ float tile[32][33];
    int ez = blockIdx.z;
    int k0 = blockIdx.y * 32;
    int n0 = blockIdx.x * 32;
    int tx = threadIdx.x & 31, ty = threadIdx.x >> 5;

    if (blockIdx.x == 0 && blockIdx.y == 0 && blockIdx.z == 0 && threadIdx.x < EE)
        g_cnt[threadIdx.x] = 0;

    const float* src = w2 + (size_t)ez * HHv * DD;
    #pragma unroll
    for (int r = 0; r < 32; r += 8)
        tile[ty + r][tx] = src[(size_t)(k0 + ty + r) * DD + n0 + tx];
    __syncthreads();

    __nv_bfloat16* dhi = g_w2Thi + (size_t)ez * DD * HHv;
    __nv_bfloat16* dlo = g_w2Tlo + (size_t)ez * DD * HHv;
    #pragma unroll
    for (int r = 0; r < 32; r += 8) {
        float v = tile[tx][ty + r];
        __nv_bfloat16 hi = __float2bfloat16(v);
        __nv_bfloat16 lo = __float2bfloat16(v - __bfloat162float(hi));
        size_t o = (size_t)(n0 + ty + r) * HHv + k0 + tx;
        dhi[o] = hi; dlo[o] = lo;
    }
}

// ---------------- warp-resident gate + qsim + hidden (1 warp per row) ----------------
__global__ __launch_bounds__(256) void k_gate_qsim_w(
    const float* __restrict__ Xext,
    const float* __restrict__ gW, const float* __restrict__ gb,
    const float* __restrict__ qp, const float* __restrict__ rW,
    const float* __restrict__ rb,
    int blk)
{
    __shared__ float2 stbuf[8][256];     // per-warp CNOT permute buffer
    const unsigned FULL = 0xffffffffu;
    int wid = threadIdx.x >> 5;
    int lane = threadIdx.x & 31;
    int b = blockIdx.x * 8 + wid;

    const float* X = (blk == 0) ? Xext : g_X1;
    const float4* xr4 = (const float4*)(X + (size_t)b * DD);

    float4 xv[8];
    #pragma unroll
    for (int j = 0; j < 8; j++) xv[j] = xr4[j * 32 + lane];

    // ---- gate logits ----
    float acc[EE];
    #pragma unroll
    for (int e = 0; e < EE; e++) acc[e] = 0.f;
    const float* gwb = gW + (size_t)blk * DD * EE;
    #pragma unroll
    for (int j = 0; j < 8; j++) {
        int d0 = (j * 32 + lane) * 4;
        const float xs[4] = { xv[j].x, xv[j].y, xv[j].z, xv[j].w };
        #pragma unroll
        for (int c = 0; c < 4; c++) {
            const float4* gr = (const float4*)(gwb + (size_t)(d0 + c) * EE);
            float4 g0 = gr[0], g1 = gr[1];
            float xvv = xs[c];
            acc[0] += xvv * g0.x; acc[1] += xvv * g0.y; acc[2] += xvv * g0.z; acc[3] += xvv * g0.w;
            acc[4] += xvv * g1.x; acc[5] += xvv * g1.y; acc[6] += xvv * g1.z; acc[7] += xvv * g1.w;
        }
    }
    #pragma unroll
    for (int e = 0; e < EE; e++) {
        #pragma unroll
        for (int o = 16; o > 0; o >>= 1) acc[e] += __shfl_xor_sync(FULL, acc[e], o);
    }

    // ---- softmax + top2 (redundant on all lanes) ----
    float l[EE], mx = -1e30f;
    #pragma unroll
    for (int e = 0; e < EE; e++) { l[e] = acc[e] + gb[blk * EE + e]; mx = fmaxf(mx, l[e]); }
    float sum = 0.f;
    #pragma unroll
    for (int e = 0; e < EE; e++) { l[e] = expf(l[e] - mx); sum += l[e]; }
    float inv = 1.f / sum;
    #pragma unroll
    for (int e = 0; e < EE; e++) l[e] *= inv;
    int i0 = 0;
    #pragma unroll
    for (int e = 1; e < EE; e++) if (l[e] > l[i0]) i0 = e;
    int i1 = (i0 == 0) ? 1 : 0;
    #pragma unroll
    for (int e = 0; e < EE; e++) if (e != i1 && e != i0 && l[e] > l[i1]) i1 = e;
    float p0 = l[i0], p1 = l[i1];
    float w1 = 1.f / (1.f + expf(p0 - p1));
    float w0 = 1.f - w1;
    if (lane == 0) {
        int pos0 = atomicAdd(&g_cnt[i0], 1); g_list[i0 * BB + pos0] = b * 2 + 0;
        int pos1 = atomicAdd(&g_cnt[i1], 1); g_list[i1 * BB + pos1] = b * 2 + 1;
        g_sel[b] = make_int2(i0, i1);
        g_wgt[b] = make_float2(w0, w1);
    }

    // ---- per-qubit angle cos/sin ----
    float v0 = __shfl_sync(FULL, xv[0].x, lane >> 2);
    float v1 = __shfl_sync(FULL, xv[0].y, lane >> 2);
    float v2 = __shfl_sync(FULL, xv[0].z, lane >> 2);
    float v3 = __shfl_sync(FULL, xv[0].w, lane >> 2);
    float xq = (lane & 2) ? ((lane & 1) ? v3 : v2) : ((lane & 1) ? v1 : v0);
    float cq_own, sq_own;
    sincosf(0.5f * xq, &sq_own, &cq_own);
    float cqv[NQv], sqv[NQv];
    #pragma unroll
    for (int q = 0; q < NQv; q++) {
        cqv[q] = __shfl_sync(FULL, cq_own, q);
        sqv[q] = __shfl_sync(FULL, sq_own, q);
    }

    int esel[2] = { i0, i1 };
    float wsel[2] = { w0, w1 };
    float2* sw = stbuf[wid];

    #pragma unroll
    for (int s = 0; s < 2; s++) {
        int e = esel[s];

        float2 st[8];
        #pragma unroll
        for (int j = 0; j < 8; j++) {
            int idx = lane * 8 + j;
            float v = 1.f;
            #pragma unroll
            for (int q = 0; q < NQv; q++)
                v *= ((idx >> (NQv - 1 - q)) & 1) ? sqv[q] : cqv[q];
            st[j] = make_float2(v, 0.f);
        }

        const float* qpe = qp + (size_t)(blk * EE + e) * NLv * NQv * 3;
        #pragma unroll
        for (int lyr = 0; lyr < NLv; lyr++) {
            const float* pp = qpe + (lyr * NQv + (lane & 7)) * 3;
            float phi = pp[0], th = pp[1], om = pp[2];
            float c, sn; sincosf(0.5f * th, &sn, &c);
            float sa, ca; sincosf(0.5f * (phi + om), &sa, &ca);
            float sb, cb; sincosf(0.5f * (phi - om), &sb, &cb);
            float o00r = ca * c,  o00i = -sa * c;
            float o11r = ca * c,  o11i =  sa * c;
            float o01r = -cb * sn, o01i = -sb * sn;
            float o10r =  cb * sn, o10i = -sb * sn;

            #pragma unroll
            for (int q = 0; q < NQv; q++) {
                float M00r = __shfl_sync(FULL, o00r, q), M00i = __shfl_sync(FULL, o00i, q);
                float M01r = __shfl_sync(FULL, o01r, q), M01i = __shfl_sync(FULL, o01i, q);
                float M10r = __shfl_sync(FULL, o10r, q), M10i = __shfl_sync(FULL, o10i, q);
                float M11r = __shfl_sync(FULL, o11r, q), M11i = __shfl_sync(FULL, o11i, q);
                const int pb = NQv - 1 - q;
                if (pb >= 3) {
                    int msk = 1 << (pb - 3);
                    int bit = (lane >> (pb - 3)) & 1;
                    float Msr = bit ? M11r : M00r, Msi = bit ? M11i : M00i;
                    float Mpr = bit ? M10r : M01r, Mpi = bit ? M10i : M01i;
                    #pragma unroll
                    for (int j = 0; j < 8; j++) {
                        float px = __shfl_xor_sync(FULL, st[j].x, msk);
                        float py = __shfl_xor_sync(FULL, st[j].y, msk);
                        float nx = Msr * st[j].x - Msi * st[j].y + Mpr * px - Mpi * py;
                        float ny = Msr * st[j].y + Msi * st[j].x + Mpr * py + Mpi * px;
                        st[j] = make_float2(nx, ny);
                    }
                } else {
                    const int m = 1 << pb;
                    #pragma unroll
                    for (int j = 0; j < 8; j++) {
                        if (!(j & m)) {
                            float2 a0 = st[j], a1 = st[j | m];
                            float2 n0, n1;
                            n0.x = M00r * a0.x - M00i * a0.y + M01r * a1.x - M01i * a1.y;
                            n0.y = M00r * a0.y + M00i * a0.x + M01r * a1.y + M01i * a1.x;
                            n1.x = M10r * a0.x - M10i * a0.y + M11r * a1.x - M11i * a1.y;
                            n1.y = M10r * a0.y + M10i * a0.x + M11r * a1.y + M11i * a1.x;
                            st[j] = n0; st[j | m] = n1;
                        }
                    }
                }
            }
            #pragma unroll
            for (int j = 0; j < 8; j++) sw[lane * 8 + j] = st[j];
            __syncwarp();
            #pragma unroll
            for (int j = 0; j < 8; j++) {
                int idx = lane * 8 + j;
                int jsrc = idx;
                #pragma unroll
                for (int q = NQv - 2; q >= 0; q--) {
                    int pc = NQv - 1 - q, pt = NQv - 2 - q;
                    jsrc ^= ((jsrc >> pc) & 1) << pt;
                }
                st[j] = sw[jsrc];
            }
            __syncwarp();
        }

        // ---- Z expectations ----
        float zp[NQv];
        #pragma unroll
        for (int k = 0; k < NQv; k++) zp[k] = 0.f;
        #pragma unroll
        for (int j = 0; j < 8; j++) {
            int idx = lane * 8 + j;
            float p = st[j].x * st[j].x + st[j].y * st[j].y;
            #pragma unroll
            for (int k = 0; k < NQv; k++)
                zp[k] += ((idx >> (NQv - 1 - k)) & 1) ? -p : p;
        }
        #pragma unroll
        for (int k = 0; k < NQv; k++) {
            #pragma unroll
            for (int o = 16; o > 0; o >>= 1) zp[k] += __shfl_xor_sync(FULL, zp[k], o);
        }

        // ---- hidden: h = relu(q @ rW + rb) * gate_w -> packed {hi-pair, lo-pair} ----
        float wgt = wsel[s];
        const float* rWe = rW + (size_t)(blk * EE + e) * NQv * HHv;
        const float4* rbe = (const float4*)(rb + (size_t)(blk * EE + e) * HHv);
        size_t slot = (size_t)b * 2 + s;
        uint4* dpk = (uint4*)(g_Hpk + slot * (HHv / 2));
        #pragma unroll
        for (int j = 0; j < 8; j++) {
            int g = j * 32 + lane;
            float4 a = rbe[g];
            #pragma unroll
            for (int jj = 0; jj < NQv; jj++) {
                float4 wv = ((const float4*)(rWe + (size_t)jj * HHv))[g];
                a.x += zp[jj] * wv.x; a.y += zp[jj] * wv.y;
                a.z += zp[jj] * wv.z; a.w += zp[jj] * wv.w;
            }
            a.x = fmaxf(a.x, 0.f) * wgt; a.y = fmaxf(a.y, 0.f) * wgt;
            a.z = fmaxf(a.z, 0.f) * wgt; a.w = fmaxf(a.w, 0.f) * wgt;
            __nv_bfloat16 hx = __float2bfloat16(a.x), hy = __float2bfloat16(a.y);
            __nv_bfloat16 hz = __float2bfloat16(a.z), hw = __float2bfloat16(a.w);
            __nv_bfloat16 lx = __float2bfloat16(a.x - __bfloat162float(hx));
            __nv_bfloat16 ly = __float2bfloat16(a.y - __bfloat162float(hy));
            __nv_bfloat16 lz = __float2bfloat16(a.z - __bfloat162float(hz));
            __nv_bfloat16 lw = __float2bfloat16(a.w - __bfloat162float(hw));
            uint4 pk;
            pk.x = ((uint32_t)__bfloat16_as_ushort(hy) << 16) | __bfloat16_as_ushort(hx);
            pk.y = ((uint32_t)__bfloat16_as_ushort(ly) << 16) | __bfloat16_as_ushort(lx);
            pk.z = ((uint32_t)__bfloat16_as_ushort(hw) << 16) | __bfloat16_as_ushort(hz);
            pk.w = ((uint32_t)__bfloat16_as_ushort(lw) << 16) | __bfloat16_as_ushort(lz);
            dpk[g] = pk;
        }
    }
}

// ---------------- grouped expert GEMM via mma.sync (bf16x3, A from global) ----------------
__global__ __launch_bounds__(256, 2) void k_moe_gemm_mma(int blk)
{
    extern __shared__ char dsm[];
    __shared__ int rows[BM];

    int e = blockIdx.z;
    int n_e = g_cnt[e];
    int m0 = blockIdx.y * BM;
    if (m0 >= n_e) return;
    int n0 = blockIdx.x * BN;

    int tid = threadIdx.x;
    int lane = tid & 31;
    int wid = tid >> 5;
    int warp_m = wid >> 2;     // 0..1 -> 64 rows each
    int warp_n = wid & 3;      // 0..3 -> 32 cols each

    if (tid < BM) {
        int m = m0 + tid;
        rows[tid] = (m < n_e) ? g_list[e * BB + m] : -1;
    }
    __syncthreads();

    uint32_t sbase = smem_u32(dsm);
    const __nv_bfloat16* Bhi = g_w2Thi + (size_t)(blk * EE + e) * DD * HHv;
    const __nv_bfloat16* Blo = g_w2Tlo + (size_t)(blk * EE + e) * DD * HHv;

    // per-lane A fragment base pointers (2 rows per mg, packed hi/lo pairs)
    const uint2* aptr[8];
    #pragma unroll
    for (int mg = 0; mg < 4; mg++) {
        #pragma unroll
        for (int rr = 0; rr < 2; rr++) {
            int row = warp_m * 64 + mg * 16 + (lane >> 2) + rr * 8;
            int slot = rows[row];
            aptr[mg * 2 + rr] = (slot >= 0) ? (g_Hpk + (size_t)slot * (HHv / 2)) : g_zpk;
        }
    }

    // ---- B-only stage loader ----
    auto load_B = [&](int chunk, int stage) {
        uint32_t sb = sbase + stage * BSTG_BYT;
        int kofs = chunk * BK;
        #pragma unroll
        for (int j = 0; j < 2; j++) {
            int idx = tid + 256 * j;       // 0..511
            int row = idx >> 2;
            int seg = idx & 3;
            uint32_t doff = (uint32_t)(row * RSTR + seg * 16);
            size_t boff = (size_t)(n0 + row) * HHv + kofs + seg * 8;
            cp16(sb + 0 * TILE_BYT + doff, Bhi + boff);
            cp16(sb + 1 * TILE_BYT + doff, Blo + boff);
        }
    };

    float acc[4][4][4];
    #pragma unroll
    for (int i = 0; i < 4; i++)
        #pragma unroll
        for (int j = 0; j < 4; j++)
            #pragma unroll
            for (int q = 0; q < 4; q++) acc[i][j][q] = 0.f;

    uint32_t b_row = (uint32_t)(warp_n * 32 + (lane & 7) + ((lane >> 4) & 1) * 8);
    uint32_t b_colp = (uint32_t)(((lane >> 3) & 1) * 16);

    load_B(0, 0); cp_commit();
    load_B(1, 1); cp_commit();
    load_B(2, 2); cp_commit();

    for (int i = 0; i < NCH; i++) {
        if (i < NCH - 2) asm volatile("cp.async.wait_group 2;" ::: "memory");
        else             asm volatile("cp.async.wait_group 0;" ::: "memory");
        __syncthreads();
        if (i + 3 < NCH) { load_B(i + 3, (i + 3) & 3); cp_commit(); }

        uint32_t sb = sbase + (i & 3) * BSTG_BYT;
        uint32_t sBhi = sb, sBlo = sb + TILE_BYT;

        #pragma unroll
        for (int kk = 0; kk < BK / 16; kk++) {
            uint32_t kbyte = (uint32_t)(kk * 32);
            uint32_t bh[2][4], bl[2][4];
            #pragma unroll
            for (int ng = 0; ng < 2; ng++)
                ldm4(bh[ng], sBhi + (b_row + ng * 16) * RSTR + kbyte + b_colp);
            #pragma unroll
            for (int ng = 0; ng < 2; ng++)
                ldm4(bl[ng], sBlo + (b_row + ng * 16) * RSTR + kbyte + b_colp);

            int pk = i * 16 + kk * 8 + (lane & 3);
            #pragma unroll
            for (int mg = 0; mg < 4; mg++) {
                uint2 v00 = aptr[mg * 2 + 0][pk];
                uint2 v10 = aptr[mg * 2 + 1][pk];
                uint2 v01 = aptr[mg * 2 + 0][pk + 4];
                uint2 v11 = aptr[mg * 2 + 1][pk + 4];
                uint32_t ah[4] = { v00.x, v10.x, v01.x, v11.x };
                uint32_t al[4] = { v00.y, v10.y, v01.y, v11.y };
                #pragma unroll
                for (int nf = 0; nf < 4; nf++)
                    mma16816(acc[mg][nf], ah, &bh[nf >> 1][(nf & 1) * 2]);
                #pragma unroll
                for (int nf = 0; nf < 4; nf++)
                    mma16816(acc[mg][nf], ah, &bl[nf >> 1][(nf & 1) * 2]);
                #pragma unroll
                for (int nf = 0; nf < 4; nf++)
                    mma16816(acc[mg][nf], al, &bh[nf >> 1][(nf & 1) * 2]);
            }
        }
    }

    // ---- epilogue: per-slot non-atomic stores ----
    int mb = warp_m * 64 + (lane >> 2);
    int nb = n0 + warp_n * 32 + (lane & 3) * 2;
    #pragma unroll
    for (int mg = 0; mg < 4; mg++) {
        int r0 = mb + mg * 16;
        int r1 = r0 + 8;
        int s0 = rows[r0], s1 = rows[r1];
        #pragma unroll
        for (int nf = 0; nf < 4; nf++) {
            int n = nb + nf * 8;
            if (s0 >= 0) *(float2*)(g_Eout + (size_t)s0 * DD + n) = make_float2(acc[mg][nf][0], acc[mg][nf][1]);
            if (s1 >= 0) *(float2*)(g_Eout + (size_t)s1 * DD + n) = make_float2(acc[mg][nf][2], acc[mg][nf][3]);
        }
    }
}

// ---------------- layernorm (residual + bias + both slot outputs) ----------------
__device__ __forceinline__ float blockReduceSum(float v, float* red)
{
    __syncthreads();
    int lane = threadIdx.x & 31;
    int w = threadIdx.x >> 5;
    #pragma unroll
    for (int o = 16; o > 0; o >>= 1) v += __shfl_xor_sync(0xffffffffu, v, o);
    if (lane == 0) red[w] = v;
    __syncthreads();
    float r = (lane < 8) ? red[lane] : 0.f;
    #pragma unroll
    for (int o = 4; o > 0; o >>= 1) r += __shfl_xor_sync(0xffffffffu, r, o);
    return r;
}

__global__ __launch_bounds__(256) void k_ln(
    const float* __restrict__ Xext, const float* __restrict__ b2,
    const float* __restrict__ gam, const float* __restrict__ bet,
    float* __restrict__ Yext, int blk)
{
    __shared__ float red[32];
    __shared__ float bc[2];
    int b = blockIdx.x, tid = threadIdx.x;
    float* Y = (blk == 0) ? g_X1 : Yext;
    const float* xrow = ((blk == 0) ? Xext : g_X1) + (size_t)b * DD;

    if (blk == 0 && blockIdx.x == 0 && tid < EE) g_cnt[tid] = 0;  // reset for next block

    int2 se = g_sel[b];
    float2 wv = g_wgt[b];
    const float* b2a = b2 + ((size_t)blk * EE + se.x) * DD;
    const float* b2b = b2 + ((size_t)blk * EE + se.y) * DD;
    const float* e0 = g_Eout + (size_t)(2 * b) * DD;
    const float* e1 = e0 + DD;

    float v[4];
    float s = 0.f;
    #pragma unroll
    for (int i = 0; i < 4; i++) {
        int n = tid + 256 * i;
        v[i] = xrow[n] + wv.x * b2a[n] + wv.y * b2b[n] + e0[n] + e1[n];
        s += v[i];
    }
    float tot = blockReduceSum(s, red);
    if (tid == 0) bc[0] = tot;
    __syncthreads();
    float mu = bc[0] * (1.f / 1024.f);

    float s2 = 0.f;
    #pragma unroll
    for (int i = 0; i < 4; i++) { float d = v[i] - mu; s2 += d * d; }
    float tot2 = blockReduceSum(s2, red);
    if (tid == 0) bc[1] = tot2;
    __syncthreads();
    float inv = 1.f / sqrtf(bc[1] * (1.f / 1024.f) + 1e-5f);

    #pragma unroll
    for (int i = 0; i < 4; i++) {
        int n = tid + 256 * i;
        Y[(size_t)b * DD + n] = (v[i] - mu) * inv * gam[blk * DD + n] + bet[blk * DD + n];
    }
}

// ---------------- launch ----------------
extern "C" void kernel_launch(void* const* d_in, const int* in_sizes, int n_in,
                              void* d_out, int out_size)
{
    (void)in_sizes; (void)n_in; (void)out_size;
    const float* x  = (const float*)d_in[0];
    const float* gW = (const float*)d_in[1];
    const float* gb = (const float*)d_in[2];
    const float* qp = (const float*)d_in[3];
    const float* rW = (const float*)d_in[4];
    const float* rb = (const float*)d_in[5];
    const float* w2 = (const float*)d_in[6];
    const float* b2 = (const float*)d_in[7];
    const float* lg = (const float*)d_in[8];
    const float* lb = (const float*)d_in[9];
    float* out = (float*)d_out;

    cudaFuncSetAttribute(k_moe_gemm_mma, cudaFuncAttributeMaxDynamicSharedMemorySize, GEMM_SMEM);

    // one-time per launch: transpose + bf16-split all expert w2 matrices (+ reset cnt)
    k_w2t<<<dim3(DD / 32, HHv / 32, 2 * EE), 256>>>(w2);

    for (int blk = 0; blk < 2; blk++) {
        k_gate_qsim_w<<<BB / 8, 256>>>(x, gW, gb, qp, rW, rb, blk);
        dim3 g2(DD / BN, BB / BM, EE);
        k_moe_gemm_mma<<<g2, 256, GEMM_SMEM>>>(blk);
        k_ln<<<BB, 256>>>(x, b2, lg, lb, out, blk);
    }
}

// round 12
// speedup vs baseline: 1.4211x; 1.4211x over previous
#include <cuda_runtime.h>
#include <cuda_bf16.h>
#include <cstdint>
#include <math.h>

#define BB 8192
#define DD 1024
#define EE 8
#define NQv 8
#define NLv 2
#define HHv 1024

// ---------------- scratch (static device globals: no allocation) ----------------
__device__ float g_X1[(size_t)BB * DD];                 // inter-block activations
__device__ __nv_bfloat16 g_Hhi[(size_t)BB * 2 * HHv];   // hidden, bf16 hi
__device__ __nv_bfloat16 g_Hlo[(size_t)BB * 2 * HHv];   // hidden, bf16 lo
__device__ float g_Eout[(size_t)BB * 2 * DD];           // per-slot GEMM output
__device__ __nv_bfloat16 g_w2Thi[(size_t)2 * EE * DD * HHv]; // w2^T [e][n][k] hi
__device__ __nv_bfloat16 g_w2Tlo[(size_t)2 * EE * DD * HHv]; // w2^T [e][n][k] lo
__device__ float g_qv[(size_t)BB * 2 * NQv];            // per-slot Z expectations
__device__ int   g_cnt[EE];
__device__ int   g_list[EE * BB];                       // entries encode row*2+slot
__device__ int2   g_sel[BB];                            // per-row selected experts
__device__ float2 g_wgt[BB];                            // per-row gate weights

// ---------------- generic PTX helpers ----------------
static __device__ __forceinline__ uint32_t smem_u32(const void* p) {
    uint32_t a;
    asm("{ .reg .u64 t; cvta.to.shared.u64 t, %1; cvt.u32.u64 %0, t; }" : "=r"(a) : "l"(p));
    return a;
}
static __device__ __forceinline__ void cp16(uint32_t dst, const void* src) {
    asm volatile("cp.async.cg.shared.global [%0], [%1], 16;" :: "r"(dst), "l"(src) : "memory");
}
static __device__ __forceinline__ void cp16z(uint32_t dst, const void* src, int srcsize) {
    asm volatile("cp.async.cg.shared.global [%0], [%1], 16, %2;" :: "r"(dst), "l"(src), "r"(srcsize) : "memory");
}
static __device__ __forceinline__ void cp_commit() {
    asm volatile("cp.async.commit_group;" ::: "memory");
}
static __device__ __forceinline__ void ldm4(uint32_t* r, uint32_t addr) {
    asm volatile("ldmatrix.sync.aligned.m8n8.x4.shared.b16 {%0,%1,%2,%3}, [%4];"
        : "=r"(r[0]), "=r"(r[1]), "=r"(r[2]), "=r"(r[3]) : "r"(addr));
}
static __device__ __forceinline__ void mma16816(float* c, const uint32_t* a, const uint32_t* b) {
    asm volatile("mma.sync.aligned.m16n8k16.row.col.f32.bf16.bf16.f32 "
        "{%0,%1,%2,%3}, {%4,%5,%6,%7}, {%8,%9}, {%0,%1,%2,%3};"
        : "+f"(c[0]), "+f"(c[1]), "+f"(c[2]), "+f"(c[3])
        : "r"(a[0]), "r"(a[1]), "r"(a[2]), "r"(a[3]), "r"(b[0]), "r"(b[1]));
}

// ---------------- GEMM tile config (R7: BK=32, 2-stage, 2 CTA/SM) ----------------
#define BM 128
#define BN 128
#define BK 32
#define NCH (HHv / BK)                 // 32
#define RSTR 80                         // bytes per SMEM row (16B-aligned, conflict-free)
#define TILE_BYT (BM * RSTR)            // 10240
#define STAGE_BYT (4 * TILE_BYT)        // 40960: Ahi, Alo, Bhi, Blo
#define GEMM_SMEM (2 * STAGE_BYT)       // 81920

// ---------------- w2 -> w2^T, split fp32 into bf16 hi/lo (+ reset cnt) ----------------
__global__ __launch_bounds__(256) void k_w2t(const float* __restrict__ w2)
{
    __shared__ float tile[32][33];
    int ez = blockIdx.z;
    int k0 = blockIdx.y * 32;
    int n0 = blockIdx.x * 32;
    int tx = threadIdx.x & 31, ty = threadIdx.x >> 5;

    if (blockIdx.x == 0 && blockIdx.y == 0 && blockIdx.z == 0 && threadIdx.x < EE)
        g_cnt[threadIdx.x] = 0;

    const float* src = w2 + (size_t)ez * HHv * DD;
    #pragma unroll
    for (int r = 0; r < 32; r += 8)
        tile[ty + r][tx] = src[(size_t)(k0 + ty + r) * DD + n0 + tx];
    __syncthreads();

    __nv_bfloat16* dhi = g_w2Thi + (size_t)ez * DD * HHv;
    __nv_bfloat16* dlo = g_w2Tlo + (size_t)ez * DD * HHv;
    #pragma unroll
    for (int r = 0; r < 32; r += 8) {
        float v = tile[tx][ty + r];
        __nv_bfloat16 hi = __float2bfloat16(v);
        __nv_bfloat16 lo = __float2bfloat16(v - __bfloat162float(hi));
        size_t o = (size_t)(n0 + ty + r) * HHv + k0 + tx;
        dhi[o] = hi; dlo[o] = lo;
    }
}

// ---------------- warp-resident gate + qsim (1 warp per row; q vectors out) ----------------
__global__ __launch_bounds__(256) void k_gate_qsim_w(
    const float* __restrict__ Xext,
    const float* __restrict__ gW, const float* __restrict__ gb,
    const float* __restrict__ qp,
    int blk)
{
    __shared__ float2 stbuf[8][256];     // per-warp CNOT permute buffer
    const unsigned FULL = 0xffffffffu;
    int wid = threadIdx.x >> 5;
    int lane = threadIdx.x & 31;
    int b = blockIdx.x * 8 + wid;

    const float* X = (blk == 0) ? Xext : g_X1;
    const float4* xr4 = (const float4*)(X + (size_t)b * DD);

    float4 xv[8];
    #pragma unroll
    for (int j = 0; j < 8; j++) xv[j] = xr4[j * 32 + lane];

    // ---- gate logits ----
    float acc[EE];
    #pragma unroll
    for (int e = 0; e < EE; e++) acc[e] = 0.f;
    const float* gwb = gW + (size_t)blk * DD * EE;
    #pragma unroll
    for (int j = 0; j < 8; j++) {
        int d0 = (j * 32 + lane) * 4;
        const float xs[4] = { xv[j].x, xv[j].y, xv[j].z, xv[j].w };
        #pragma unroll
        for (int c = 0; c < 4; c++) {
            const float4* gr = (const float4*)(gwb + (size_t)(d0 + c) * EE);
            float4 g0 = gr[0], g1 = gr[1];
            float xvv = xs[c];
            acc[0] += xvv * g0.x; acc[1] += xvv * g0.y; acc[2] += xvv * g0.z; acc[3] += xvv * g0.w;
            acc[4] += xvv * g1.x; acc[5] += xvv * g1.y; acc[6] += xvv * g1.z; acc[7] += xvv * g1.w;
        }
    }
    #pragma unroll
    for (int e = 0; e < EE; e++) {
        #pragma unroll
        for (int o = 16; o > 0; o >>= 1) acc[e] += __shfl_xor_sync(FULL, acc[e], o);
    }

    // ---- softmax + top2 (redundant on all lanes) ----
    float l[EE], mx = -1e30f;
    #pragma unroll
    for (int e = 0; e < EE; e++) { l[e] = acc[e] + gb[blk * EE + e]; mx = fmaxf(mx, l[e]); }
    float sum = 0.f;
    #pragma unroll
    for (int e = 0; e < EE; e++) { l[e] = expf(l[e] - mx); sum += l[e]; }
    float inv = 1.f / sum;
    #pragma unroll
    for (int e = 0; e < EE; e++) l[e] *= inv;
    int i0 = 0;
    #pragma unroll
    for (int e = 1; e < EE; e++) if (l[e] > l[i0]) i0 = e;
    int i1 = (i0 == 0) ? 1 : 0;
    #pragma unroll
    for (int e = 0; e < EE; e++) if (e != i1 && e != i0 && l[e] > l[i1]) i1 = e;
    float p0 = l[i0], p1 = l[i1];
    float w1 = 1.f / (1.f + expf(p0 - p1));
    float w0 = 1.f - w1;
    if (lane == 0) {
        int pos0 = atomicAdd(&g_cnt[i0], 1); g_list[i0 * BB + pos0] = b * 2 + 0;
        int pos1 = atomicAdd(&g_cnt[i1], 1); g_list[i1 * BB + pos1] = b * 2 + 1;
        g_sel[b] = make_int2(i0, i1);
        g_wgt[b] = make_float2(w0, w1);
    }

    // ---- per-qubit angle cos/sin ----
    float v0 = __shfl_sync(FULL, xv[0].x, lane >> 2);
    float v1 = __shfl_sync(FULL, xv[0].y, lane >> 2);
    float v2 = __shfl_sync(FULL, xv[0].z, lane >> 2);
    float v3 = __shfl_sync(FULL, xv[0].w, lane >> 2);
    float xq = (lane & 2) ? ((lane & 1) ? v3 : v2) : ((lane & 1) ? v1 : v0);
    float cq_own, sq_own;
    sincosf(0.5f * xq, &sq_own, &cq_own);
    float cqv[NQv], sqv[NQv];
    #pragma unroll
    for (int q = 0; q < NQv; q++) {
        cqv[q] = __shfl_sync(FULL, cq_own, q);
        sqv[q] = __shfl_sync(FULL, sq_own, q);
    }

    int esel[2] = { i0, i1 };
    float2* sw = stbuf[wid];

    #pragma unroll
    for (int s = 0; s < 2; s++) {
        int e = esel[s];

        float2 st[8];
        #pragma unroll
        for (int j = 0; j < 8; j++) {
            int idx = lane * 8 + j;
            float v = 1.f;
            #pragma unroll
            for (int q = 0; q < NQv; q++)
                v *= ((idx >> (NQv - 1 - q)) & 1) ? sqv[q] : cqv[q];
            st[j] = make_float2(v, 0.f);
        }

        const float* qpe = qp + (size_t)(blk * EE + e) * NLv * NQv * 3;
        #pragma unroll
        for (int lyr = 0; lyr < NLv; lyr++) {
            const float* pp = qpe + (lyr * NQv + (lane & 7)) * 3;
            float phi = pp[0], th = pp[1], om = pp[2];
            float c, sn; sincosf(0.5f * th, &sn, &c);
            float sa, ca; sincosf(0.5f * (phi + om), &sa, &ca);
            float sb, cb; sincosf(0.5f * (phi - om), &sb, &cb);
            float o00r = ca * c,  o00i = -sa * c;
            float o11r = ca * c,  o11i =  sa * c;
            float o01r = -cb * sn, o01i = -sb * sn;
            float o10r =  cb * sn, o10i = -sb * sn;

            #pragma unroll
            for (int q = 0; q < NQv; q++) {
                float M00r = __shfl_sync(FULL, o00r, q), M00i = __shfl_sync(FULL, o00i, q);
                float M01r = __shfl_sync(FULL, o01r, q), M01i = __shfl_sync(FULL, o01i, q);
                float M10r = __shfl_sync(FULL, o10r, q), M10i = __shfl_sync(FULL, o10i, q);
                float M11r = __shfl_sync(FULL, o11r, q), M11i = __shfl_sync(FULL, o11i, q);
                const int pb = NQv - 1 - q;
                if (pb >= 3) {
                    int msk = 1 << (pb - 3);
                    int bit = (lane >> (pb - 3)) & 1;
                    float Msr = bit ? M11r : M00r, Msi = bit ? M11i : M00i;
                    float Mpr = bit ? M10r : M01r, Mpi = bit ? M10i : M01i;
                    #pragma unroll
                    for (int j = 0; j < 8; j++) {
                        float px = __shfl_xor_sync(FULL, st[j].x, msk);
                        float py = __shfl_xor_sync(FULL, st[j].y, msk);
                        float nx = Msr * st[j].x - Msi * st[j].y + Mpr * px - Mpi * py;
                        float ny = Msr * st[j].y + Msi * st[j].x + Mpr * py + Mpi * px;
                        st[j] = make_float2(nx, ny);
                    }
                } else {
                    const int m = 1 << pb;
                    #pragma unroll
                    for (int j = 0; j < 8; j++) {
                        if (!(j & m)) {
                            float2 a0 = st[j], a1 = st[j | m];
                            float2 n0, n1;
                            n0.x = M00r * a0.x - M00i * a0.y + M01r * a1.x - M01i * a1.y;
                            n0.y = M00r * a0.y + M00i * a0.x + M01r * a1.y + M01i * a1.x;
                            n1.x = M10r * a0.x - M10i * a0.y + M11r * a1.x - M11i * a1.y;
                            n1.y = M10r * a0.y + M10i * a0.x + M11r * a1.y + M11i * a1.x;
                            st[j] = n0; st[j | m] = n1;
                        }
                    }
                }
            }
            #pragma unroll
            for (int j = 0; j < 8; j++) sw[lane * 8 + j] = st[j];
            __syncwarp();
            #pragma unroll
            for (int j = 0; j < 8; j++) {
                int idx = lane * 8 + j;
                int jsrc = idx;
                #pragma unroll
                for (int q = NQv - 2; q >= 0; q--) {
                    int pc = NQv - 1 - q, pt = NQv - 2 - q;
                    jsrc ^= ((jsrc >> pc) & 1) << pt;
                }
                st[j] = sw[jsrc];
            }
            __syncwarp();
        }

        // ---- Z expectations -> g_qv ----
        float zp[NQv];
        #pragma unroll
        for (int k = 0; k < NQv; k++) zp[k] = 0.f;
        #pragma unroll
        for (int j = 0; j < 8; j++) {
            int idx = lane * 8 + j;
            float p = st[j].x * st[j].x + st[j].y * st[j].y;
            #pragma unroll
            for (int k = 0; k < NQv; k++)
                zp[k] += ((idx >> (NQv - 1 - k)) & 1) ? -p : p;
        }
        #pragma unroll
        for (int k = 0; k < NQv; k++) {
            #pragma unroll
            for (int o = 16; o > 0; o >>= 1) zp[k] += __shfl_xor_sync(FULL, zp[k], o);
        }
        if (lane == 0) {
            size_t slot = (size_t)b * 2 + s;
            *(float4*)(g_qv + slot * NQv)     = make_float4(zp[0], zp[1], zp[2], zp[3]);
            *(float4*)(g_qv + slot * NQv + 4) = make_float4(zp[4], zp[5], zp[6], zp[7]);
        }
    }
}

// ---------------- grouped hidden layer: rW in SMEM, per-expert slot lists ----------------
#define HSLOTS 128
__global__ __launch_bounds__(256) void k_hidden(
    const float* __restrict__ rW, const float* __restrict__ rb, int blk)
{
    __shared__ float s_rW[NQv * HHv];   // 32KB
    __shared__ float s_rb[HHv];         // 4KB

    int e = blockIdx.x;
    int tile = blockIdx.y;
    int n_e = g_cnt[e];
    if (tile * HSLOTS >= n_e) return;

    int t = threadIdx.x;

    // stage rW + rb
    const float4* src = (const float4*)(rW + (size_t)(blk * EE + e) * NQv * HHv);
    float4* dst = (float4*)s_rW;
    #pragma unroll
    for (int i = 0; i < 8; i++) dst[t + 256 * i] = src[t + 256 * i];
    ((float4*)s_rb)[t] = ((const float4*)(rb + (size_t)(blk * EE + e) * HHv))[t];
    __syncthreads();

    float4 rbv = ((const float4*)s_rb)[t];
    const float4* w4[NQv];
    #pragma unroll
    for (int j = 0; j < NQv; j++) w4[j] = (const float4*)(s_rW + j * HHv);

    int hi_end = min(n_e, (tile + 1) * HSLOTS);
    for (int idx = tile * HSLOTS; idx < hi_end; idx++) {
        int entry = g_list[e * BB + idx];
        float2 wpair = g_wgt[entry >> 1];
        float wgt = (entry & 1) ? wpair.y : wpair.x;
        const float* q = g_qv + (size_t)entry * NQv;
        float qr[NQv];
        #pragma unroll
        for (int j = 0; j < NQv; j++) qr[j] = __ldg(q + j);

        float4 a = rbv;
        #pragma unroll
        for (int j = 0; j < NQv; j++) {
            float4 wv = w4[j][t];
            a.x += qr[j] * wv.x; a.y += qr[j] * wv.y;
            a.z += qr[j] * wv.z; a.w += qr[j] * wv.w;
        }
        a.x = fmaxf(a.x, 0.f) * wgt; a.y = fmaxf(a.y, 0.f) * wgt;
        a.z = fmaxf(a.z, 0.f) * wgt; a.w = fmaxf(a.w, 0.f) * wgt;

        __nv_bfloat16 hx = __float2bfloat16(a.x), hy = __float2bfloat16(a.y);
        __nv_bfloat16 hz = __float2bfloat16(a.z), hw = __float2bfloat16(a.w);
        __nv_bfloat16 lx = __float2bfloat16(a.x - __bfloat162float(hx));
        __nv_bfloat16 ly = __float2bfloat16(a.y - __bfloat162float(hy));
        __nv_bfloat16 lz = __float2bfloat16(a.z - __bfloat162float(hz));
        __nv_bfloat16 lw = __float2bfloat16(a.w - __bfloat162float(hw));
        uint2 uh, ul;
        uh.x = ((uint32_t)__bfloat16_as_ushort(hy) << 16) | __bfloat16_as_ushort(hx);
        uh.y = ((uint32_t)__bfloat16_as_ushort(hw) << 16) | __bfloat16_as_ushort(hz);
        ul.x = ((uint32_t)__bfloat16_as_ushort(ly) << 16) | __bfloat16_as_ushort(lx);
        ul.y = ((uint32_t)__bfloat16_as_ushort(lw) << 16) | __bfloat16_as_ushort(lz);
        ((uint2*)(g_Hhi + (size_t)entry * HHv))[t] = uh;
        ((uint2*)(g_Hlo + (size_t)entry * HHv))[t] = ul;
    }
}

// ---------------- grouped expert GEMM via mma.sync (R7 version, verbatim) ----------------
__global__ __launch_bounds__(256, 2) void k_moe_gemm_mma(int blk)
{
    extern __shared__ char dsm[];
    __shared__ int rows[BM];

    int e = blockIdx.z;
    int n_e = g_cnt[e];
    int m0 = blockIdx.y * BM;
    if (m0 >= n_e) return;
    int n0 = blockIdx.x * BN;

    int tid = threadIdx.x;
    int lane = tid & 31;
    int wid = tid >> 5;
    int warp_m = wid >> 2;
    int warp_n = wid & 3;

    if (tid < BM) {
        int m = m0 + tid;
        rows[tid] = (m < n_e) ? g_list[e * BB + m] : -1;
    }
    __syncthreads();

    uint32_t sbase = smem_u32(dsm);
    const __nv_bfloat16* Bhi = g_w2Thi + (size_t)(blk * EE + e) * DD * HHv;
    const __nv_bfloat16* Blo = g_w2Tlo + (size_t)(blk * EE + e) * DD * HHv;

    auto load_stage = [&](int chunk, int stage) {
        uint32_t sb = sbase + stage * STAGE_BYT;
        int kofs = chunk * BK;
        #pragma unroll
        for (int j = 0; j < 2; j++) {
            int idx = tid + 256 * j;
            int row = idx >> 2;
            int seg = idx & 3;
            uint32_t doff = (uint32_t)(row * RSTR + seg * 16);
            int slot = rows[row];
            int sz = (slot >= 0) ? 16 : 0;
            size_t off = (size_t)(slot >= 0 ? slot : 0) * HHv + kofs + seg * 8;
            cp16z(sb + 0 * TILE_BYT + doff, g_Hhi + off, sz);
            cp16z(sb + 1 * TILE_BYT + doff, g_Hlo + off, sz);
            size_t boff = (size_t)(n0 + row) * HHv + kofs + seg * 8;
            cp16(sb + 2 * TILE_BYT + doff, Bhi + boff);
            cp16(sb + 3 * TILE_BYT + doff, Blo + boff);
        }
    };

    float acc[4][4][4];
    #pragma unroll
    for (int i = 0; i < 4; i++)
        #pragma unroll
        for (int j = 0; j < 4; j++)
            #pragma unroll
            for (int q = 0; q < 4; q++) acc[i][j][q] = 0.f;

    uint32_t a_row = (uint32_t)(warp_m * 64 + (lane & 15));
    uint32_t a_colp = (uint32_t)((lane >> 4) * 16);
    uint32_t b_row = (uint32_t)(warp_n * 32 + (lane & 7) + ((lane >> 4) & 1) * 8);
    uint32_t b_colp = (uint32_t)(((lane >> 3) & 1) * 16);

    load_stage(0, 0);
    cp_commit();

    for (int i = 0; i < NCH; i++) {
        if (i + 1 < NCH) { load_stage(i + 1, (i + 1) & 1); cp_commit(); }
        if (i + 1 < NCH) asm volatile("cp.async.wait_group 1;" ::: "memory");
        else             asm volatile("cp.async.wait_group 0;" ::: "memory");
        __syncthreads();

        uint32_t sb = sbase + (i & 1) * STAGE_BYT;
        uint32_t sAhi = sb, sAlo = sb + TILE_BYT, sBhi = sb + 2 * TILE_BYT, sBlo = sb + 3 * TILE_BYT;

        #pragma unroll
        for (int kk = 0; kk < BK / 16; kk++) {
            uint32_t kbyte = (uint32_t)(kk * 32);
            uint32_t ah[4][4], al[4][4], bh[2][4], bl[2][4];

            #pragma unroll
            for (int mg = 0; mg < 4; mg++)
                ldm4(ah[mg], sAhi + (a_row + mg * 16) * RSTR + kbyte + a_colp);
            #pragma unroll
            for (int ng = 0; ng < 2; ng++)
                ldm4(bh[ng], sBhi + (b_row + ng * 16) * RSTR + kbyte + b_colp);
            #pragma unroll
            for (int ng = 0; ng < 2; ng++)
                ldm4(bl[ng], sBlo + (b_row + ng * 16) * RSTR + kbyte + b_colp);

            #pragma unroll
            for (int mg = 0; mg < 4; mg++)
                #pragma unroll
                for (int nf = 0; nf < 4; nf++)
                    mma16816(acc[mg][nf], ah[mg], &bh[nf >> 1][(nf & 1) * 2]);
            #pragma unroll
            for (int mg = 0; mg < 4; mg++)
                #pragma unroll
                for (int nf = 0; nf < 4; nf++)
                    mma16816(acc[mg][nf], ah[mg], &bl[nf >> 1][(nf & 1) * 2]);
            #pragma unroll
            for (int mg = 0; mg < 4; mg++)
                ldm4(al[mg], sAlo + (a_row + mg * 16) * RSTR + kbyte + a_colp);
            #pragma unroll
            for (int mg = 0; mg < 4; mg++)
                #pragma unroll
                for (int nf = 0; nf < 4; nf++)
                    mma16816(acc[mg][nf], al[mg], &bh[nf >> 1][(nf & 1) * 2]);
        }
        __syncthreads();
    }

    int mb = warp_m * 64 + (lane >> 2);
    int nb = n0 + warp_n * 32 + (lane & 3) * 2;
    #pragma unroll
    for (int mg = 0; mg < 4; mg++) {
        int r0 = mb + mg * 16;
        int r1 = r0 + 8;
        int s0 = rows[r0], s1 = rows[r1];
        #pragma unroll
        for (int nf = 0; nf < 4; nf++) {
            int n = nb + nf * 8;
            if (s0 >= 0) *(float2*)(g_Eout + (size_t)s0 * DD + n) = make_float2(acc[mg][nf][0], acc[mg][nf][1]);
            if (s1 >= 0) *(float2*)(g_Eout + (size_t)s1 * DD + n) = make_float2(acc[mg][nf][2], acc[mg][nf][3]);
        }
    }
}

// ---------------- layernorm (residual + bias + both slot outputs) ----------------
__device__ __forceinline__ float blockReduceSum(float v, float* red)
{
    __syncthreads();
    int lane = threadIdx.x & 31;
    int w = threadIdx.x >> 5;
    #pragma unroll
    for (int o = 16; o > 0; o >>= 1) v += __shfl_xor_sync(0xffffffffu, v, o);
    if (lane == 0) red[w] = v;
    __syncthreads();
    float r = (lane < 8) ? red[lane] : 0.f;
    #pragma unroll
    for (int o = 4; o > 0; o >>= 1) r += __shfl_xor_sync(0xffffffffu, r, o);
    return r;
}

__global__ __launch_bounds__(256) void k_ln(
    const float* __restrict__ Xext, const float* __restrict__ b2,
    const float* __restrict__ gam, const float* __restrict__ bet,
    float* __restrict__ Yext, int blk)
{
    __shared__ float red[32];
    __shared__ float bc[2];
    int b = blockIdx.x, tid = threadIdx.x;
    float* Y = (blk == 0) ? g_X1 : Yext;
    const float* xrow = ((blk == 0) ? Xext : g_X1) + (size_t)b * DD;

    if (blk == 0 && blockIdx.x == 0 && tid < EE) g_cnt[tid] = 0;  // reset for next block

    int2 se = g_sel[b];
    float2 wv = g_wgt[b];
    const float* b2a = b2 + ((size_t)blk * EE + se.x) * DD;
    const float* b2b = b2 + ((size_t)blk * EE + se.y) * DD;
    const float* e0 = g_Eout + (size_t)(2 * b) * DD;
    const float* e1 = e0 + DD;

    float v[4];
    float s = 0.f;
    #pragma unroll
    for (int i = 0; i < 4; i++) {
        int n = tid + 256 * i;
        v[i] = xrow[n] + wv.x * b2a[n] + wv.y * b2b[n] + e0[n] + e1[n];
        s += v[i];
    }
    float tot = blockReduceSum(s, red);
    if (tid == 0) bc[0] = tot;
    __syncthreads();
    float mu = bc[0] * (1.f / 1024.f);

    float s2 = 0.f;
    #pragma unroll
    for (int i = 0; i < 4; i++) { float d = v[i] - mu; s2 += d * d; }
    float tot2 = blockReduceSum(s2, red);
    if (tid == 0) bc[1] = tot2;
    __syncthreads();
    float inv = 1.f / sqrtf(bc[1] * (1.f / 1024.f) + 1e-5f);

    #pragma unroll
    for (int i = 0; i < 4; i++) {
        int n = tid + 256 * i;
        Y[(size_t)b * DD + n] = (v[i] - mu) * inv * gam[blk * DD + n] + bet[blk * DD + n];
    }
}

// ---------------- launch ----------------
extern "C" void kernel_launch(void* const* d_in, const int* in_sizes, int n_in,
                              void* d_out, int out_size)
{
    (void)in_sizes; (void)n_in; (void)out_size;
    const float* x  = (const float*)d_in[0];
    const float* gW = (const float*)d_in[1];
    const float* gb = (const float*)d_in[2];
    const float* qp = (const float*)d_in[3];
    const float* rW = (const float*)d_in[4];
    const float* rb = (const float*)d_in[5];
    const float* w2 = (const float*)d_in[6];
    const float* b2 = (const float*)d_in[7];
    const float* lg = (const float*)d_in[8];
    const float* lb = (const float*)d_in[9];
    float* out = (float*)d_out;

    cudaFuncSetAttribute(k_moe_gemm_mma, cudaFuncAttributeMaxDynamicSharedMemorySize, GEMM_SMEM);

    // one-time per launch: transpose + bf16-split all expert w2 matrices (+ reset cnt)
    k_w2t<<<dim3(DD / 32, HHv / 32, 2 * EE), 256>>>(w2);

    for (int blk = 0; blk < 2; blk++) {
        k_gate_qsim_w<<<BB / 8, 256>>>(x, gW, gb, qp, blk);
        k_hidden<<<dim3(EE, (2 * BB) / HSLOTS), 256>>>(rW, rb, blk);
        dim3 g2(DD / BN, BB / BM, EE);
        k_moe_gemm_mma<<<g2, 256, GEMM_SMEM>>>(blk);
        k_ln<<<BB, 256>>>(x, b2, lg, lb, out, blk);
    }
}

// round 13
// speedup vs baseline: 1.7636x; 1.2410x over previous
#include <cuda_runtime.h>
#include <cuda_fp16.h>
#include <cstdint>
#include <math.h>

#define BB 8192
#define DD 1024
#define EE 8
#define NQv 8
#define NLv 2
#define HHv 1024

// ---------------- scratch (static device globals: no allocation) ----------------
__device__ float g_X1[(size_t)BB * DD];                 // inter-block activations
__device__ __half g_Hf[(size_t)BB * 2 * HHv];           // hidden, fp16 (single)
__device__ float g_Eout[(size_t)BB * 2 * DD];           // per-slot GEMM output
__device__ __half g_w2Thi[(size_t)2 * EE * DD * HHv];   // w2^T [e][n][k] fp16 hi
__device__ __half g_w2Tlo[(size_t)2 * EE * DD * HHv];   // w2^T [e][n][k] fp16 lo
__device__ float g_qv[(size_t)BB * 2 * NQv];            // per-slot Z expectations
__device__ int   g_cnt[EE];
__device__ int   g_list[EE * BB];                       // entries encode row*2+slot
__device__ int2   g_sel[BB];                            // per-row selected experts
__device__ float2 g_wgt[BB];                            // per-row gate weights

// ---------------- generic PTX helpers ----------------
static __device__ __forceinline__ uint32_t smem_u32(const void* p) {
    uint32_t a;
    asm("{ .reg .u64 t; cvta.to.shared.u64 t, %1; cvt.u32.u64 %0, t; }" : "=r"(a) : "l"(p));
    return a;
}
static __device__ __forceinline__ void cp16(uint32_t dst, const void* src) {
    asm volatile("cp.async.cg.shared.global [%0], [%1], 16;" :: "r"(dst), "l"(src) : "memory");
}
static __device__ __forceinline__ void cp16z(uint32_t dst, const void* src, int srcsize) {
    asm volatile("cp.async.cg.shared.global [%0], [%1], 16, %2;" :: "r"(dst), "l"(src), "r"(srcsize) : "memory");
}
static __device__ __forceinline__ void cp_commit() {
    asm volatile("cp.async.commit_group;" ::: "memory");
}
static __device__ __forceinline__ void ldm4(uint32_t* r, uint32_t addr) {
    asm volatile("ldmatrix.sync.aligned.m8n8.x4.shared.b16 {%0,%1,%2,%3}, [%4];"
        : "=r"(r[0]), "=r"(r[1]), "=r"(r[2]), "=r"(r[3]) : "r"(addr));
}
static __device__ __forceinline__ void mma16816(float* c, const uint32_t* a, const uint32_t* b) {
    asm volatile("mma.sync.aligned.m16n8k16.row.col.f32.f16.f16.f32 "
        "{%0,%1,%2,%3}, {%4,%5,%6,%7}, {%8,%9}, {%0,%1,%2,%3};"
        : "+f"(c[0]), "+f"(c[1]), "+f"(c[2]), "+f"(c[3])
        : "r"(a[0]), "r"(a[1]), "r"(a[2]), "r"(a[3]), "r"(b[0]), "r"(b[1]));
}

// ---------------- GEMM tile config (fp16x2: A single, B hi/lo; 3-stage ring) ----------------
#define BM 128
#define BN 128
#define BK 32
#define NCH (HHv / BK)                 // 32
#define RSTR 80                         // bytes per SMEM row (16B-aligned, conflict-free)
#define TILE_BYT (BM * RSTR)            // 10240
#define STAGE_BYT (3 * TILE_BYT)        // 30720: A, Bhi, Blo
#define NSTAGE 3
#define GEMM_SMEM (NSTAGE * STAGE_BYT)  // 92160

// ---------------- w2 -> w2^T, split fp32 into fp16 hi/lo (+ reset cnt) ----------------
__global__ __launch_bounds__(256) void k_w2t(const float* __restrict__ w2)
{
    __shared__ float tile[32][33];
    int ez = blockIdx.z;
    int k0 = blockIdx.y * 32;
    int n0 = blockIdx.x * 32;
    int tx = threadIdx.x & 31, ty = threadIdx.x >> 5;

    if (blockIdx.x == 0 && blockIdx.y == 0 && blockIdx.z == 0 && threadIdx.x < EE)
        g_cnt[threadIdx.x] = 0;

    const float* src = w2 + (size_t)ez * HHv * DD;
    #pragma unroll
    for (int r = 0; r < 32; r += 8)
        tile[ty + r][tx] = src[(size_t)(k0 + ty + r) * DD + n0 + tx];
    __syncthreads();

    __half* dhi = g_w2Thi + (size_t)ez * DD * HHv;
    __half* dlo = g_w2Tlo + (size_t)ez * DD * HHv;
    #pragma unroll
    for (int r = 0; r < 32; r += 8) {
        float v = tile[tx][ty + r];
        __half hi = __float2half(v);
        __half lo = __float2half(v - __half2float(hi));
        size_t o = (size_t)(n0 + ty + r) * HHv + k0 + tx;
        dhi[o] = hi; dlo[o] = lo;
    }
}

// ---------------- warp-resident gate + qsim (1 warp per row; q vectors out) ----------------
__global__ __launch_bounds__(256) void k_gate_qsim_w(
    const float* __restrict__ Xext,
    const float* __restrict__ gW, const float* __restrict__ gb,
    const float* __restrict__ qp,
    int blk)
{
    __shared__ float2 stbuf[8][256];     // per-warp CNOT permute buffer
    const unsigned FULL = 0xffffffffu;
    int wid = threadIdx.x >> 5;
    int lane = threadIdx.x & 31;
    int b = blockIdx.x * 8 + wid;

    const float* X = (blk == 0) ? Xext : g_X1;
    const float4* xr4 = (const float4*)(X + (size_t)b * DD);

    float4 xv[8];
    #pragma unroll
    for (int j = 0; j < 8; j++) xv[j] = xr4[j * 32 + lane];

    // ---- gate logits ----
    float acc[EE];
    #pragma unroll
    for (int e = 0; e < EE; e++) acc[e] = 0.f;
    const float* gwb = gW + (size_t)blk * DD * EE;
    #pragma unroll
    for (int j = 0; j < 8; j++) {
        int d0 = (j * 32 + lane) * 4;
        const float xs[4] = { xv[j].x, xv[j].y, xv[j].z, xv[j].w };
        #pragma unroll
        for (int c = 0; c < 4; c++) {
            const float4* gr = (const float4*)(gwb + (size_t)(d0 + c) * EE);
            float4 g0 = gr[0], g1 = gr[1];
            float xvv = xs[c];
            acc[0] += xvv * g0.x; acc[1] += xvv * g0.y; acc[2] += xvv * g0.z; acc[3] += xvv * g0.w;
            acc[4] += xvv * g1.x; acc[5] += xvv * g1.y; acc[6] += xvv * g1.z; acc[7] += xvv * g1.w;
        }
    }
    #pragma unroll
    for (int e = 0; e < EE; e++) {
        #pragma unroll
        for (int o = 16; o > 0; o >>= 1) acc[e] += __shfl_xor_sync(FULL, acc[e], o);
    }

    // ---- softmax + top2 (redundant on all lanes) ----
    float l[EE], mx = -1e30f;
    #pragma unroll
    for (int e = 0; e < EE; e++) { l[e] = acc[e] + gb[blk * EE + e]; mx = fmaxf(mx, l[e]); }
    float sum = 0.f;
    #pragma unroll
    for (int e = 0; e < EE; e++) { l[e] = expf(l[e] - mx); sum += l[e]; }
    float inv = 1.f / sum;
    #pragma unroll
    for (int e = 0; e < EE; e++) l[e] *= inv;
    int i0 = 0;
    #pragma unroll
    for (int e = 1; e < EE; e++) if (l[e] > l[i0]) i0 = e;
    int i1 = (i0 == 0) ? 1 : 0;
    #pragma unroll
    for (int e = 0; e < EE; e++) if (e != i1 && e != i0 && l[e] > l[i1]) i1 = e;
    float p0 = l[i0], p1 = l[i1];
    float w1 = 1.f / (1.f + expf(p0 - p1));
    float w0 = 1.f - w1;
    if (lane == 0) {
        int pos0 = atomicAdd(&g_cnt[i0], 1); g_list[i0 * BB + pos0] = b * 2 + 0;
        int pos1 = atomicAdd(&g_cnt[i1], 1); g_list[i1 * BB + pos1] = b * 2 + 1;
        g_sel[b] = make_int2(i0, i1);
        g_wgt[b] = make_float2(w0, w1);
    }

    // ---- per-qubit angle cos/sin ----
    float v0 = __shfl_sync(FULL, xv[0].x, lane >> 2);
    float v1 = __shfl_sync(FULL, xv[0].y, lane >> 2);
    float v2 = __shfl_sync(FULL, xv[0].z, lane >> 2);
    float v3 = __shfl_sync(FULL, xv[0].w, lane >> 2);
    float xq = (lane & 2) ? ((lane & 1) ? v3 : v2) : ((lane & 1) ? v1 : v0);
    float cq_own, sq_own;
    sincosf(0.5f * xq, &sq_own, &cq_own);
    float cqv[NQv], sqv[NQv];
    #pragma unroll
    for (int q = 0; q < NQv; q++) {
        cqv[q] = __shfl_sync(FULL, cq_own, q);
        sqv[q] = __shfl_sync(FULL, sq_own, q);
    }

    int esel[2] = { i0, i1 };
    float2* sw = stbuf[wid];

    #pragma unroll
    for (int s = 0; s < 2; s++) {
        int e = esel[s];

        float2 st[8];
        #pragma unroll
        for (int j = 0; j < 8; j++) {
            int idx = lane * 8 + j;
            float v = 1.f;
            #pragma unroll
            for (int q = 0; q < NQv; q++)
                v *= ((idx >> (NQv - 1 - q)) & 1) ? sqv[q] : cqv[q];
            st[j] = make_float2(v, 0.f);
        }

        const float* qpe = qp + (size_t)(blk * EE + e) * NLv * NQv * 3;
        #pragma unroll
        for (int lyr = 0; lyr < NLv; lyr++) {
            const float* pp = qpe + (lyr * NQv + (lane & 7)) * 3;
            float phi = pp[0], th = pp[1], om = pp[2];
            float c, sn; sincosf(0.5f * th, &sn, &c);
            float sa, ca; sincosf(0.5f * (phi + om), &sa, &ca);
            float sb, cb; sincosf(0.5f * (phi - om), &sb, &cb);
            float o00r = ca * c,  o00i = -sa * c;
            float o11r = ca * c,  o11i =  sa * c;
            float o01r = -cb * sn, o01i = -sb * sn;
            float o10r =  cb * sn, o10i = -sb * sn;

            #pragma unroll
            for (int q = 0; q < NQv; q++) {
                float M00r = __shfl_sync(FULL, o00r, q), M00i = __shfl_sync(FULL, o00i, q);
                float M01r = __shfl_sync(FULL, o01r, q), M01i = __shfl_sync(FULL, o01i, q);
                float M10r = __shfl_sync(FULL, o10r, q), M10i = __shfl_sync(FULL, o10i, q);
                float M11r = __shfl_sync(FULL, o11r, q), M11i = __shfl_sync(FULL, o11i, q);
                const int pb = NQv - 1 - q;
                if (pb >= 3) {
                    int msk = 1 << (pb - 3);
                    int bit = (lane >> (pb - 3)) & 1;
                    float Msr = bit ? M11r : M00r, Msi = bit ? M11i : M00i;
                    float Mpr = bit ? M10r : M01r, Mpi = bit ? M10i : M01i;
                    #pragma unroll
                    for (int j = 0; j < 8; j++) {
                        float px = __shfl_xor_sync(FULL, st[j].x, msk);
                        float py = __shfl_xor_sync(FULL, st[j].y, msk);
                        float nx = Msr * st[j].x - Msi * st[j].y + Mpr * px - Mpi * py;
                        float ny = Msr * st[j].y + Msi * st[j].x + Mpr * py + Mpi * px;
                        st[j] = make_float2(nx, ny);
                    }
                } else {
                    const int m = 1 << pb;
                    #pragma unroll
                    for (int j = 0; j < 8; j++) {
                        if (!(j & m)) {
                            float2 a0 = st[j], a1 = st[j | m];
                            float2 n0, n1;
                            n0.x = M00r * a0.x - M00i * a0.y + M01r * a1.x - M01i * a1.y;
                            n0.y = M00r * a0.y + M00i * a0.x + M01r * a1.y + M01i * a1.x;
                            n1.x = M10r * a0.x - M10i * a0.y + M11r * a1.x - M11i * a1.y;
                            n1.y = M10r * a0.y + M10i * a0.x + M11r * a1.y + M11i * a1.x;
                            st[j] = n0; st[j | m] = n1;
                        }
                    }
                }
            }
            #pragma unroll
            for (int j = 0; j < 8; j++) sw[lane * 8 + j] = st[j];
            __syncwarp();
            #pragma unroll
            for (int j = 0; j < 8; j++) {
                int idx = lane * 8 + j;
                int jsrc = idx;
                #pragma unroll
                for (int q = NQv - 2; q >= 0; q--) {
                    int pc = NQv - 1 - q, pt = NQv - 2 - q;
                    jsrc ^= ((jsrc >> pc) & 1) << pt;
                }
                st[j] = sw[jsrc];
            }
            __syncwarp();
        }

        // ---- Z expectations -> g_qv ----
        float zp[NQv];
        #pragma unroll
        for (int k = 0; k < NQv; k++) zp[k] = 0.f;
        #pragma unroll
        for (int j = 0; j < 8; j++) {
            int idx = lane * 8 + j;
            float p = st[j].x * st[j].x + st[j].y * st[j].y;
            #pragma unroll
            for (int k = 0; k < NQv; k++)
                zp[k] += ((idx >> (NQv - 1 - k)) & 1) ? -p : p;
        }
        #pragma unroll
        for (int k = 0; k < NQv; k++) {
            #pragma unroll
            for (int o = 16; o > 0; o >>= 1) zp[k] += __shfl_xor_sync(FULL, zp[k], o);
        }
        if (lane == 0) {
            size_t slot = (size_t)b * 2 + s;
            *(float4*)(g_qv + slot * NQv)     = make_float4(zp[0], zp[1], zp[2], zp[3]);
            *(float4*)(g_qv + slot * NQv + 4) = make_float4(zp[4], zp[5], zp[6], zp[7]);
        }
    }
}

// ---------------- grouped hidden layer: rW in SMEM, per-expert slot lists ----------------
#define HSLOTS 128
__global__ __launch_bounds__(256) void k_hidden(
    const float* __restrict__ rW, const float* __restrict__ rb, int blk)
{
    __shared__ float s_rW[NQv * HHv];   // 32KB
    __shared__ float s_rb[HHv];         // 4KB

    int e = blockIdx.x;
    int tile = blockIdx.y;
    int n_e = g_cnt[e];
    if (tile * HSLOTS >= n_e) return;

    int t = threadIdx.x;

    const float4* src = (const float4*)(rW + (size_t)(blk * EE + e) * NQv * HHv);
    float4* dst = (float4*)s_rW;
    #pragma unroll
    for (int i = 0; i < 8; i++) dst[t + 256 * i] = src[t + 256 * i];
    ((float4*)s_rb)[t] = ((const float4*)(rb + (size_t)(blk * EE + e) * HHv))[t];
    __syncthreads();

    float4 rbv = ((const float4*)s_rb)[t];
    const float4* w4[NQv];
    #pragma unroll
    for (int j = 0; j < NQv; j++) w4[j] = (const float4*)(s_rW + j * HHv);

    int hi_end = min(n_e, (tile + 1) * HSLOTS);
    for (int idx = tile * HSLOTS; idx < hi_end; idx++) {
        int entry = g_list[e * BB + idx];
        float2 wpair = g_wgt[entry >> 1];
        float wgt = (entry & 1) ? wpair.y : wpair.x;
        const float* q = g_qv + (size_t)entry * NQv;
        float qr[NQv];
        #pragma unroll
        for (int j = 0; j < NQv; j++) qr[j] = __ldg(q + j);

        float4 a = rbv;
        #pragma unroll
        for (int j = 0; j < NQv; j++) {
            float4 wv = w4[j][t];
            a.x += qr[j] * wv.x; a.y += qr[j] * wv.y;
            a.z += qr[j] * wv.z; a.w += qr[j] * wv.w;
        }
        a.x = fmaxf(a.x, 0.f) * wgt; a.y = fmaxf(a.y, 0.f) * wgt;
        a.z = fmaxf(a.z, 0.f) * wgt; a.w = fmaxf(a.w, 0.f) * wgt;

        __half hx = __float2half(a.x), hy = __float2half(a.y);
        __half hz = __float2half(a.z), hw = __float2half(a.w);
        uint2 uh;
        uh.x = ((uint32_t)__half_as_ushort(hy) << 16) | __half_as_ushort(hx);
        uh.y = ((uint32_t)__half_as_ushort(hw) << 16) | __half_as_ushort(hz);
        ((uint2*)(g_Hf + (size_t)entry * HHv))[t] = uh;
    }
}

// ---------------- grouped expert GEMM via mma.sync (fp16: A single, B hi/lo) ----------------
__global__ __launch_bounds__(256, 2) void k_moe_gemm_mma(int blk)
{
    extern __shared__ char dsm[];
    __shared__ int rows[BM];

    int e = blockIdx.z;
    int n_e = g_cnt[e];
    int m0 = blockIdx.y * BM;
    if (m0 >= n_e) return;
    int n0 = blockIdx.x * BN;

    int tid = threadIdx.x;
    int lane = tid & 31;
    int wid = tid >> 5;
    int warp_m = wid >> 2;
    int warp_n = wid & 3;

    if (tid < BM) {
        int m = m0 + tid;
        rows[tid] = (m < n_e) ? g_list[e * BB + m] : -1;
    }
    __syncthreads();

    uint32_t sbase = smem_u32(dsm);
    const __half* Bhi = g_w2Thi + (size_t)(blk * EE + e) * DD * HHv;
    const __half* Blo = g_w2Tlo + (size_t)(blk * EE + e) * DD * HHv;

    auto load_stage = [&](int chunk, int stage) {
        uint32_t sb = sbase + stage * STAGE_BYT;
        int kofs = chunk * BK;
        #pragma unroll
        for (int j = 0; j < 2; j++) {
            int idx = tid + 256 * j;
            int row = idx >> 2;
            int seg = idx & 3;
            uint32_t doff = (uint32_t)(row * RSTR + seg * 16);
            int slot = rows[row];
            int sz = (slot >= 0) ? 16 : 0;
            size_t off = (size_t)(slot >= 0 ? slot : 0) * HHv + kofs + seg * 8;
            cp16z(sb + 0 * TILE_BYT + doff, g_Hf + off, sz);
            size_t boff = (size_t)(n0 + row) * HHv + kofs + seg * 8;
            cp16(sb + 1 * TILE_BYT + doff, Bhi + boff);
            cp16(sb + 2 * TILE_BYT + doff, Blo + boff);
        }
    };

    float acc[4][4][4];
    #pragma unroll
    for (int i = 0; i < 4; i++)
        #pragma unroll
        for (int j = 0; j < 4; j++)
            #pragma unroll
            for (int q = 0; q < 4; q++) acc[i][j][q] = 0.f;

    uint32_t a_row = (uint32_t)(warp_m * 64 + (lane & 15));
    uint32_t a_colp = (uint32_t)((lane >> 4) * 16);
    uint32_t b_row = (uint32_t)(warp_n * 32 + (lane & 7) + ((lane >> 4) & 1) * 8);
    uint32_t b_colp = (uint32_t)(((lane >> 3) & 1) * 16);

    load_stage(0, 0); cp_commit();
    load_stage(1, 1); cp_commit();

    for (int i = 0; i < NCH; i++) {
        if (i + 1 < NCH) asm volatile("cp.async.wait_group 1;" ::: "memory");
        else             asm volatile("cp.async.wait_group 0;" ::: "memory");
        __syncthreads();
        int nx = i + 2;
        if (nx < NCH) { load_stage(nx, nx % NSTAGE); cp_commit(); }

        uint32_t sb = sbase + (i % NSTAGE) * STAGE_BYT;
        uint32_t sA = sb, sBhi = sb + TILE_BYT, sBlo = sb + 2 * TILE_BYT;

        #pragma unroll
        for (int kk = 0; kk < BK / 16; kk++) {
            uint32_t kbyte = (uint32_t)(kk * 32);
            uint32_t ah[4][4], bh[2][4], bl[2][4];

            #pragma unroll
            for (int mg = 0; mg < 4; mg++)
                ldm4(ah[mg], sA + (a_row + mg * 16) * RSTR + kbyte + a_colp);
            #pragma unroll
            for (int ng = 0; ng < 2; ng++)
                ldm4(bh[ng], sBhi + (b_row + ng * 16) * RSTR + kbyte + b_colp);
            #pragma unroll
            for (int ng = 0; ng < 2; ng++)
                ldm4(bl[ng], sBlo + (b_row + ng * 16) * RSTR + kbyte + b_colp);

            // pass 1: A * Bhi
            #pragma unroll
            for (int mg = 0; mg < 4; mg++)
                #pragma unroll
                for (int nf = 0; nf < 4; nf++)
                    mma16816(acc[mg][nf], ah[mg], &bh[nf >> 1][(nf & 1) * 2]);
            // pass 2: A * Blo
            #pragma unroll
            for (int mg = 0; mg < 4; mg++)
                #pragma unroll
                for (int nf = 0; nf < 4; nf++)
                    mma16816(acc[mg][nf], ah[mg], &bl[nf >> 1][(nf & 1) * 2]);
        }
    }

    int mb = warp_m * 64 + (lane >> 2);
    int nb = n0 + warp_n * 32 + (lane & 3) * 2;
    #pragma unroll
    for (int mg = 0; mg < 4; mg++) {
        int r0 = mb + mg * 16;
        int r1 = r0 + 8;
        int s0 = rows[r0], s1 = rows[r1];
        #pragma unroll
        for (int nf = 0; nf < 4; nf++) {
            int n = nb + nf * 8;
            if (s0 >= 0) *(float2*)(g_Eout + (size_t)s0 * DD + n) = make_float2(acc[mg][nf][0], acc[mg][nf][1]);
            if (s1 >= 0) *(float2*)(g_Eout + (size_t)s1 * DD + n) = make_float2(acc[mg][nf][2], acc[mg][nf][3]);
        }
    }
}

// ---------------- layernorm (residual + bias + both slot outputs) ----------------
__device__ __forceinline__ float blockReduceSum(float v, float* red)
{
    __syncthreads();
    int lane = threadIdx.x & 31;
    int w = threadIdx.x >> 5;
    #pragma unroll
    for (int o = 16; o > 0; o >>= 1) v += __shfl_xor_sync(0xffffffffu, v, o);
    if (lane == 0) red[w] = v;
    __syncthreads();
    float r = (lane < 8) ? red[lane] : 0.f;
    #pragma unroll
    for (int o = 4; o > 0; o >>= 1) r += __shfl_xor_sync(0xffffffffu, r, o);
    return r;
}

__global__ __launch_bounds__(256) void k_ln(
    const float* __restrict__ Xext, const float* __restrict__ b2,
    const float* __restrict__ gam, const float* __restrict__ bet,
    float* __restrict__ Yext, int blk)
{
    __shared__ float red[32];
    __shared__ float bc[2];
    int b = blockIdx.x, tid = threadIdx.x;
    float* Y = (blk == 0) ? g_X1 : Yext;
    const float* xrow = ((blk == 0) ? Xext : g_X1) + (size_t)b * DD;

    if (blk == 0 && blockIdx.x == 0 && tid < EE) g_cnt[tid] = 0;  // reset for next block

    int2 se = g_sel[b];
    float2 wv = g_wgt[b];
    const float* b2a = b2 + ((size_t)blk * EE + se.x) * DD;
    const float* b2b = b2 + ((size_t)blk * EE + se.y) * DD;
    const float* e0 = g_Eout + (size_t)(2 * b) * DD;
    const float* e1 = e0 + DD;

    float v[4];
    float s = 0.f;
    #pragma unroll
    for (int i = 0; i < 4; i++) {
        int n = tid + 256 * i;
        v[i] = xrow[n] + wv.x * b2a[n] + wv.y * b2b[n] + e0[n] + e1[n];
        s += v[i];
    }
    float tot = blockReduceSum(s, red);
    if (tid == 0) bc[0] = tot;
    __syncthreads();
    float mu = bc[0] * (1.f / 1024.f);

    float s2 = 0.f;
    #pragma unroll
    for (int i = 0; i < 4; i++) { float d = v[i] - mu; s2 += d * d; }
    float tot2 = blockReduceSum(s2, red);
    if (tid == 0) bc[1] = tot2;
    __syncthreads();
    float inv = 1.f / sqrtf(bc[1] * (1.f / 1024.f) + 1e-5f);

    #pragma unroll
    for (int i = 0; i < 4; i++) {
        int n = tid + 256 * i;
        Y[(size_t)b * DD + n] = (v[i] - mu) * inv * gam[blk * DD + n] + bet[blk * DD + n];
    }
}

// ---------------- launch ----------------
extern "C" void kernel_launch(void* const* d_in, const int* in_sizes, int n_in,
                              void* d_out, int out_size)
{
    (void)in_sizes; (void)n_in; (void)out_size;
    const float* x  = (const float*)d_in[0];
    const float* gW = (const float*)d_in[1];
    const float* gb = (const float*)d_in[2];
    const float* qp = (const float*)d_in[3];
    const float* rW = (const float*)d_in[4];
    const float* rb = (const float*)d_in[5];
    const float* w2 = (const float*)d_in[6];
    const float* b2 = (const float*)d_in[7];
    const float* lg = (const float*)d_in[8];
    const float* lb = (const float*)d_in[9];
    float* out = (float*)d_out;

    cudaFuncSetAttribute(k_moe_gemm_mma, cudaFuncAttributeMaxDynamicSharedMemorySize, GEMM_SMEM);

    // one-time per launch: transpose + fp16-split all expert w2 matrices (+ reset cnt)
    k_w2t<<<dim3(DD / 32, HHv / 32, 2 * EE), 256>>>(w2);

    for (int blk = 0; blk < 2; blk++) {
        k_gate_qsim_w<<<BB / 8, 256>>>(x, gW, gb, qp, blk);
        k_hidden<<<dim3(EE, (2 * BB) / HSLOTS), 256>>>(rW, rb, blk);
        dim3 g2(DD / BN, BB / BM, EE);
        k_moe_gemm_mma<<<g2, 256, GEMM_SMEM>>>(blk);
        k_ln<<<BB, 256>>>(x, b2, lg, lb, out, blk);
    }
}

// round 14
// speedup vs baseline: 2.0649x; 1.1708x over previous
#include <cuda_runtime.h>
#include <cuda_fp16.h>
#include <cstdint>
#include <math.h>

#define BB 8192
#define DD 1024
#define EE 8
#define NQv 8
#define NLv 2
#define HHv 1024

// ---------------- scratch (static device globals: no allocation) ----------------
__device__ float g_X1[(size_t)BB * DD];                 // inter-block activations
__device__ __half g_Hf[(size_t)BB * 2 * HHv];           // hidden, fp16
__device__ float g_Eout[(size_t)BB * 2 * DD];           // per-slot GEMM output
__device__ __half g_w2T[(size_t)2 * EE * DD * HHv];     // w2^T [e][n][k] fp16
__device__ float g_qv[(size_t)BB * 2 * NQv];            // per-slot Z expectations
__device__ int   g_cnt[EE];
__device__ int   g_list[EE * BB];                       // entries encode row*2+slot
__device__ int2   g_sel[BB];                            // per-row selected experts
__device__ float2 g_wgt[BB];                            // per-row gate weights

// ---------------- generic PTX helpers ----------------
static __device__ __forceinline__ uint32_t smem_u32(const void* p) {
    uint32_t a;
    asm("{ .reg .u64 t; cvta.to.shared.u64 t, %1; cvt.u32.u64 %0, t; }" : "=r"(a) : "l"(p));
    return a;
}
static __device__ __forceinline__ void cp16(uint32_t dst, const void* src) {
    asm volatile("cp.async.cg.shared.global [%0], [%1], 16;" :: "r"(dst), "l"(src) : "memory");
}
static __device__ __forceinline__ void cp16z(uint32_t dst, const void* src, int srcsize) {
    asm volatile("cp.async.cg.shared.global [%0], [%1], 16, %2;" :: "r"(dst), "l"(src), "r"(srcsize) : "memory");
}
static __device__ __forceinline__ void cp_commit() {
    asm volatile("cp.async.commit_group;" ::: "memory");
}
static __device__ __forceinline__ void ldm4(uint32_t* r, uint32_t addr) {
    asm volatile("ldmatrix.sync.aligned.m8n8.x4.shared.b16 {%0,%1,%2,%3}, [%4];"
        : "=r"(r[0]), "=r"(r[1]), "=r"(r[2]), "=r"(r[3]) : "r"(addr));
}
static __device__ __forceinline__ void mma16816(float* c, const uint32_t* a, const uint32_t* b) {
    asm volatile("mma.sync.aligned.m16n8k16.row.col.f32.f16.f16.f32 "
        "{%0,%1,%2,%3}, {%4,%5,%6,%7}, {%8,%9}, {%0,%1,%2,%3};"
        : "+f"(c[0]), "+f"(c[1]), "+f"(c[2]), "+f"(c[3])
        : "r"(a[0]), "r"(a[1]), "r"(a[2]), "r"(a[3]), "r"(b[0]), "r"(b[1]));
}

// ---------------- GEMM tile config (fp16 single-pass; 4-stage ring) ----------------
#define BM 128
#define BN 128
#define BK 32
#define NCH (HHv / BK)                 // 32
#define RSTR 80                         // bytes per SMEM row (16B-aligned, conflict-free)
#define TILE_BYT (BM * RSTR)            // 10240
#define STAGE_BYT (2 * TILE_BYT)        // 20480: A, B
#define NSTAGE 4
#define GEMM_SMEM (NSTAGE * STAGE_BYT)  // 81920

// ---------------- w2 -> w2^T fp16 (+ reset cnt) ----------------
__global__ __launch_bounds__(256) void k_w2t(const float* __restrict__ w2)
{
    __shared__ float tile[32][33];
    int ez = blockIdx.z;
    int k0 = blockIdx.y * 32;
    int n0 = blockIdx.x * 32;
    int tx = threadIdx.x & 31, ty = threadIdx.x >> 5;

    if (blockIdx.x == 0 && blockIdx.y == 0 && blockIdx.z == 0 && threadIdx.x < EE)
        g_cnt[threadIdx.x] = 0;

    const float* src = w2 + (size_t)ez * HHv * DD;
    #pragma unroll
    for (int r = 0; r < 32; r += 8)
        tile[ty + r][tx] = src[(size_t)(k0 + ty + r) * DD + n0 + tx];
    __syncthreads();

    __half* dst = g_w2T + (size_t)ez * DD * HHv;
    #pragma unroll
    for (int r = 0; r < 32; r += 8) {
        float v = tile[tx][ty + r];
        dst[(size_t)(n0 + ty + r) * HHv + k0 + tx] = __float2half(v);
    }
}

// ---------------- warp-resident gate + qsim (1 warp per row; q vectors out) ----------------
__global__ __launch_bounds__(256) void k_gate_qsim_w(
    const float* __restrict__ Xext,
    const float* __restrict__ gW, const float* __restrict__ gb,
    const float* __restrict__ qp,
    int blk)
{
    __shared__ float2 stbuf[8][256];     // per-warp CNOT permute buffer
    const unsigned FULL = 0xffffffffu;
    int wid = threadIdx.x >> 5;
    int lane = threadIdx.x & 31;
    int b = blockIdx.x * 8 + wid;

    const float* X = (blk == 0) ? Xext : g_X1;
    const float4* xr4 = (const float4*)(X + (size_t)b * DD);

    float4 xv[8];
    #pragma unroll
    for (int j = 0; j < 8; j++) xv[j] = xr4[j * 32 + lane];

    // ---- gate logits ----
    float acc[EE];
    #pragma unroll
    for (int e = 0; e < EE; e++) acc[e] = 0.f;
    const float* gwb = gW + (size_t)blk * DD * EE;
    #pragma unroll
    for (int j = 0; j < 8; j++) {
        int d0 = (j * 32 + lane) * 4;
        const float xs[4] = { xv[j].x, xv[j].y, xv[j].z, xv[j].w };
        #pragma unroll
        for (int c = 0; c < 4; c++) {
            const float4* gr = (const float4*)(gwb + (size_t)(d0 + c) * EE);
            float4 g0 = gr[0], g1 = gr[1];
            float xvv = xs[c];
            acc[0] += xvv * g0.x; acc[1] += xvv * g0.y; acc[2] += xvv * g0.z; acc[3] += xvv * g0.w;
            acc[4] += xvv * g1.x; acc[5] += xvv * g1.y; acc[6] += xvv * g1.z; acc[7] += xvv * g1.w;
        }
    }
    #pragma unroll
    for (int e = 0; e < EE; e++) {
        #pragma unroll
        for (int o = 16; o > 0; o >>= 1) acc[e] += __shfl_xor_sync(FULL, acc[e], o);
    }

    // ---- softmax + top2 (redundant on all lanes) ----
    float l[EE], mx = -1e30f;
    #pragma unroll
    for (int e = 0; e < EE; e++) { l[e] = acc[e] + gb[blk * EE + e]; mx = fmaxf(mx, l[e]); }
    float sum = 0.f;
    #pragma unroll
    for (int e = 0; e < EE; e++) { l[e] = expf(l[e] - mx); sum += l[e]; }
    float inv = 1.f / sum;
    #pragma unroll
    for (int e = 0; e < EE; e++) l[e] *= inv;
    int i0 = 0;
    #pragma unroll
    for (int e = 1; e < EE; e++) if (l[e] > l[i0]) i0 = e;
    int i1 = (i0 == 0) ? 1 : 0;
    #pragma unroll
    for (int e = 0; e < EE; e++) if (e != i1 && e != i0 && l[e] > l[i1]) i1 = e;
    float p0 = l[i0], p1 = l[i1];
    float w1 = 1.f / (1.f + expf(p0 - p1));
    float w0 = 1.f - w1;
    if (lane == 0) {
        int pos0 = atomicAdd(&g_cnt[i0], 1); g_list[i0 * BB + pos0] = b * 2 + 0;
        int pos1 = atomicAdd(&g_cnt[i1], 1); g_list[i1 * BB + pos1] = b * 2 + 1;
        g_sel[b] = make_int2(i0, i1);
        g_wgt[b] = make_float2(w0, w1);
    }

    // ---- per-qubit angle cos/sin ----
    float v0 = __shfl_sync(FULL, xv[0].x, lane >> 2);
    float v1 = __shfl_sync(FULL, xv[0].y, lane >> 2);
    float v2 = __shfl_sync(FULL, xv[0].z, lane >> 2);
    float v3 = __shfl_sync(FULL, xv[0].w, lane >> 2);
    float xq = (lane & 2) ? ((lane & 1) ? v3 : v2) : ((lane & 1) ? v1 : v0);
    float cq_own, sq_own;
    sincosf(0.5f * xq, &sq_own, &cq_own);
    float cqv[NQv], sqv[NQv];
    #pragma unroll
    for (int q = 0; q < NQv; q++) {
        cqv[q] = __shfl_sync(FULL, cq_own, q);
        sqv[q] = __shfl_sync(FULL, sq_own, q);
    }

    int esel[2] = { i0, i1 };
    float2* sw = stbuf[wid];

    #pragma unroll
    for (int s = 0; s < 2; s++) {
        int e = esel[s];

        float2 st[8];
        #pragma unroll
        for (int j = 0; j < 8; j++) {
            int idx = lane * 8 + j;
            float v = 1.f;
            #pragma unroll
            for (int q = 0; q < NQv; q++)
                v *= ((idx >> (NQv - 1 - q)) & 1) ? sqv[q] : cqv[q];
            st[j] = make_float2(v, 0.f);
        }

        const float* qpe = qp + (size_t)(blk * EE + e) * NLv * NQv * 3;
        #pragma unroll
        for (int lyr = 0; lyr < NLv; lyr++) {
            const float* pp = qpe + (lyr * NQv + (lane & 7)) * 3;
            float phi = pp[0], th = pp[1], om = pp[2];
            float c, sn; sincosf(0.5f * th, &sn, &c);
            float sa, ca; sincosf(0.5f * (phi + om), &sa, &ca);
            float sb, cb; sincosf(0.5f * (phi - om), &sb, &cb);
            float o00r = ca * c,  o00i = -sa * c;
            float o11r = ca * c,  o11i =  sa * c;
            float o01r = -cb * sn, o01i = -sb * sn;
            float o10r =  cb * sn, o10i = -sb * sn;

            #pragma unroll
            for (int q = 0; q < NQv; q++) {
                float M00r = __shfl_sync(FULL, o00r, q), M00i = __shfl_sync(FULL, o00i, q);
                float M01r = __shfl_sync(FULL, o01r, q), M01i = __shfl_sync(FULL, o01i, q);
                float M10r = __shfl_sync(FULL, o10r, q), M10i = __shfl_sync(FULL, o10i, q);
                float M11r = __shfl_sync(FULL, o11r, q), M11i = __shfl_sync(FULL, o11i, q);
                const int pb = NQv - 1 - q;
                if (pb >= 3) {
                    int msk = 1 << (pb - 3);
                    int bit = (lane >> (pb - 3)) & 1;
                    float Msr = bit ? M11r : M00r, Msi = bit ? M11i : M00i;
                    float Mpr = bit ? M10r : M01r, Mpi = bit ? M10i : M01i;
                    #pragma unroll
                    for (int j = 0; j < 8; j++) {
                        float px = __shfl_xor_sync(FULL, st[j].x, msk);
                        float py = __shfl_xor_sync(FULL, st[j].y, msk);
                        float nx = Msr * st[j].x - Msi * st[j].y + Mpr * px - Mpi * py;
                        float ny = Msr * st[j].y + Msi * st[j].x + Mpr * py + Mpi * px;
                        st[j] = make_float2(nx, ny);
                    }
                } else {
                    const int m = 1 << pb;
                    #pragma unroll
                    for (int j = 0; j < 8; j++) {
                        if (!(j & m)) {
                            float2 a0 = st[j], a1 = st[j | m];
                            float2 n0, n1;
                            n0.x = M00r * a0.x - M00i * a0.y + M01r * a1.x - M01i * a1.y;
                            n0.y = M00r * a0.y + M00i * a0.x + M01r * a1.y + M01i * a1.x;
                            n1.x = M10r * a0.x - M10i * a0.y + M11r * a1.x - M11i * a1.y;
                            n1.y = M10r * a0.y + M10i * a0.x + M11r * a1.y + M11i * a1.x;
                            st[j] = n0; st[j | m] = n1;
                        }
                    }
                }
            }
            #pragma unroll
            for (int j = 0; j < 8; j++) sw[lane * 8 + j] = st[j];
            __syncwarp();
            #pragma unroll
            for (int j = 0; j < 8; j++) {
                int idx = lane * 8 + j;
                int jsrc = idx;
                #pragma unroll
                for (int q = NQv - 2; q >= 0; q--) {
                    int pc = NQv - 1 - q, pt = NQv - 2 - q;
                    jsrc ^= ((jsrc >> pc) & 1) << pt;
                }
                st[j] = sw[jsrc];
            }
            __syncwarp();
        }

        // ---- Z expectations -> g_qv ----
        float zp[NQv];
        #pragma unroll
        for (int k = 0; k < NQv; k++) zp[k] = 0.f;
        #pragma unroll
        for (int j = 0; j < 8; j++) {
            int idx = lane * 8 + j;
            float p = st[j].x * st[j].x + st[j].y * st[j].y;
            #pragma unroll
            for (int k = 0; k < NQv; k++)
                zp[k] += ((idx >> (NQv - 1 - k)) & 1) ? -p : p;
        }
        #pragma unroll
        for (int k = 0; k < NQv; k++) {
            #pragma unroll
            for (int o = 16; o > 0; o >>= 1) zp[k] += __shfl_xor_sync(FULL, zp[k], o);
        }
        if (lane == 0) {
            size_t slot = (size_t)b * 2 + s;
            *(float4*)(g_qv + slot * NQv)     = make_float4(zp[0], zp[1], zp[2], zp[3]);
            *(float4*)(g_qv + slot * NQv + 4) = make_float4(zp[4], zp[5], zp[6], zp[7]);
        }
    }
}

// ---------------- grouped hidden layer: rW in SMEM, per-expert slot lists ----------------
#define HSLOTS 128
__global__ __launch_bounds__(256) void k_hidden(
    const float* __restrict__ rW, const float* __restrict__ rb, int blk)
{
    __shared__ float s_rW[NQv * HHv];   // 32KB
    __shared__ float s_rb[HHv];         // 4KB

    int e = blockIdx.x;
    int tile = blockIdx.y;
    int n_e = g_cnt[e];
    if (tile * HSLOTS >= n_e) return;

    int t = threadIdx.x;

    const float4* src = (const float4*)(rW + (size_t)(blk * EE + e) * NQv * HHv);
    float4* dst = (float4*)s_rW;
    #pragma unroll
    for (int i = 0; i < 8; i++) dst[t + 256 * i] = src[t + 256 * i];
    ((float4*)s_rb)[t] = ((const float4*)(rb + (size_t)(blk * EE + e) * HHv))[t];
    __syncthreads();

    float4 rbv = ((const float4*)s_rb)[t];
    const float4* w4[NQv];
    #pragma unroll
    for (int j = 0; j < NQv; j++) w4[j] = (const float4*)(s_rW + j * HHv);

    int hi_end = min(n_e, (tile + 1) * HSLOTS);
    for (int idx = tile * HSLOTS; idx < hi_end; idx++) {
        int entry = g_list[e * BB + idx];
        float2 wpair = g_wgt[entry >> 1];
        float wgt = (entry & 1) ? wpair.y : wpair.x;
        const float* q = g_qv + (size_t)entry * NQv;
        float qr[NQv];
        #pragma unroll
        for (int j = 0; j < NQv; j++) qr[j] = __ldg(q + j);

        float4 a = rbv;
        #pragma unroll
        for (int j = 0; j < NQv; j++) {
            float4 wv = w4[j][t];
            a.x += qr[j] * wv.x; a.y += qr[j] * wv.y;
            a.z += qr[j] * wv.z; a.w += qr[j] * wv.w;
        }
        a.x = fmaxf(a.x, 0.f) * wgt; a.y = fmaxf(a.y, 0.f) * wgt;
        a.z = fmaxf(a.z, 0.f) * wgt; a.w = fmaxf(a.w, 0.f) * wgt;

        __half hx = __float2half(a.x), hy = __float2half(a.y);
        __half hz = __float2half(a.z), hw = __float2half(a.w);
        uint2 uh;
        uh.x = ((uint32_t)__half_as_ushort(hy) << 16) | __half_as_ushort(hx);
        uh.y = ((uint32_t)__half_as_ushort(hw) << 16) | __half_as_ushort(hz);
        ((uint2*)(g_Hf + (size_t)entry * HHv))[t] = uh;
    }
}

// ---------------- grouped expert GEMM via mma.sync (fp16 single-pass) ----------------
__global__ __launch_bounds__(256, 2) void k_moe_gemm_mma(int blk)
{
    extern __shared__ char dsm[];
    __shared__ int rows[BM];

    int e = blockIdx.z;
    int n_e = g_cnt[e];
    int m0 = blockIdx.y * BM;
    if (m0 >= n_e) return;
    int n0 = blockIdx.x * BN;

    int tid = threadIdx.x;
    int lane = tid & 31;
    int wid = tid >> 5;
    int warp_m = wid >> 2;
    int warp_n = wid & 3;

    if (tid < BM) {
        int m = m0 + tid;
        rows[tid] = (m < n_e) ? g_list[e * BB + m] : -1;
    }
    __syncthreads();

    uint32_t sbase = smem_u32(dsm);
    const __half* Bp = g_w2T + (size_t)(blk * EE + e) * DD * HHv;

    auto load_stage = [&](int chunk, int stage) {
        uint32_t sb = sbase + stage * STAGE_BYT;
        int kofs = chunk * BK;
        #pragma unroll
        for (int j = 0; j < 2; j++) {
            int idx = tid + 256 * j;
            int row = idx >> 2;
            int seg = idx & 3;
            uint32_t doff = (uint32_t)(row * RSTR + seg * 16);
            int slot = rows[row];
            int sz = (slot >= 0) ? 16 : 0;
            size_t off = (size_t)(slot >= 0 ? slot : 0) * HHv + kofs + seg * 8;
            cp16z(sb + 0 * TILE_BYT + doff, g_Hf + off, sz);
            size_t boff = (size_t)(n0 + row) * HHv + kofs + seg * 8;
            cp16(sb + 1 * TILE_BYT + doff, Bp + boff);
        }
    };

    float acc[4][4][4];
    #pragma unroll
    for (int i = 0; i < 4; i++)
        #pragma unroll
        for (int j = 0; j < 4; j++)
            #pragma unroll
            for (int q = 0; q < 4; q++) acc[i][j][q] = 0.f;

    uint32_t a_row = (uint32_t)(warp_m * 64 + (lane & 15));
    uint32_t a_colp = (uint32_t)((lane >> 4) * 16);
    uint32_t b_row = (uint32_t)(warp_n * 32 + (lane & 7) + ((lane >> 4) & 1) * 8);
    uint32_t b_colp = (uint32_t)(((lane >> 3) & 1) * 16);

    load_stage(0, 0); cp_commit();
    load_stage(1, 1); cp_commit();
    load_stage(2, 2); cp_commit();

    for (int i = 0; i < NCH; i++) {
        if (i + 2 < NCH)      asm volatile("cp.async.wait_group 2;" ::: "memory");
        else if (i + 1 < NCH) asm volatile("cp.async.wait_group 1;" ::: "memory");
        else                  asm volatile("cp.async.wait_group 0;" ::: "memory");
        __syncthreads();
        int nx = i + 3;
        if (nx < NCH) { load_stage(nx, nx & 3); cp_commit(); }

        uint32_t sb = sbase + (i & 3) * STAGE_BYT;
        uint32_t sA = sb, sB = sb + TILE_BYT;

        #pragma unroll
        for (int kk = 0; kk < BK / 16; kk++) {
            uint32_t kbyte = (uint32_t)(kk * 32);
            uint32_t ah[4][4], bh[2][4];

            #pragma unroll
            for (int mg = 0; mg < 4; mg++)
                ldm4(ah[mg], sA + (a_row + mg * 16) * RSTR + kbyte + a_colp);
            #pragma unroll
            for (int ng = 0; ng < 2; ng++)
                ldm4(bh[ng], sB + (b_row + ng * 16) * RSTR + kbyte + b_colp);

            #pragma unroll
            for (int mg = 0; mg < 4; mg++)
                #pragma unroll
                for (int nf = 0; nf < 4; nf++)
                    mma16816(acc[mg][nf], ah[mg], &bh[nf >> 1][(nf & 1) * 2]);
        }
    }

    int mb = warp_m * 64 + (lane >> 2);
    int nb = n0 + warp_n * 32 + (lane & 3) * 2;
    #pragma unroll
    for (int mg = 0; mg < 4; mg++) {
        int r0 = mb + mg * 16;
        int r1 = r0 + 8;
        int s0 = rows[r0], s1 = rows[r1];
        #pragma unroll
        for (int nf = 0; nf < 4; nf++) {
            int n = nb + nf * 8;
            if (s0 >= 0) *(float2*)(g_Eout + (size_t)s0 * DD + n) = make_float2(acc[mg][nf][0], acc[mg][nf][1]);
            if (s1 >= 0) *(float2*)(g_Eout + (size_t)s1 * DD + n) = make_float2(acc[mg][nf][2], acc[mg][nf][3]);
        }
    }
}

// ---------------- layernorm (residual + bias + both slot outputs) ----------------
__device__ __forceinline__ float blockReduceSum(float v, float* red)
{
    __syncthreads();
    int lane = threadIdx.x & 31;
    int w = threadIdx.x >> 5;
    #pragma unroll
    for (int o = 16; o > 0; o >>= 1) v += __shfl_xor_sync(0xffffffffu, v, o);
    if (lane == 0) red[w] = v;
    __syncthreads();
    float r = (lane < 8) ? red[lane] : 0.f;
    #pragma unroll
    for (int o = 4; o > 0; o >>= 1) r += __shfl_xor_sync(0xffffffffu, r, o);
    return r;
}

__global__ __launch_bounds__(256) void k_ln(
    const float* __restrict__ Xext, const float* __restrict__ b2,
    const float* __restrict__ gam, const float* __restrict__ bet,
    float* __restrict__ Yext, int blk)
{
    __shared__ float red[32];
    __shared__ float bc[2];
    int b = blockIdx.x, tid = threadIdx.x;
    float* Y = (blk == 0) ? g_X1 : Yext;
    const float* xrow = ((blk == 0) ? Xext : g_X1) + (size_t)b * DD;

    if (blk == 0 && blockIdx.x == 0 && tid < EE) g_cnt[tid] = 0;  // reset for next block

    int2 se = g_sel[b];
    float2 wv = g_wgt[b];
    const float* b2a = b2 + ((size_t)blk * EE + se.x) * DD;
    const float* b2b = b2 + ((size_t)blk * EE + se.y) * DD;
    const float* e0 = g_Eout + (size_t)(2 * b) * DD;
    const float* e1 = e0 + DD;

    float v[4];
    float s = 0.f;
    #pragma unroll
    for (int i = 0; i < 4; i++) {
        int n = tid + 256 * i;
        v[i] = xrow[n] + wv.x * b2a[n] + wv.y * b2b[n] + e0[n] + e1[n];
        s += v[i];
    }
    float tot = blockReduceSum(s, red);
    if (tid == 0) bc[0] = tot;
    __syncthreads();
    float mu = bc[0] * (1.f / 1024.f);

    float s2 = 0.f;
    #pragma unroll
    for (int i = 0; i < 4; i++) { float d = v[i] - mu; s2 += d * d; }
    float tot2 = blockReduceSum(s2, red);
    if (tid == 0) bc[1] = tot2;
    __syncthreads();
    float inv = 1.f / sqrtf(bc[1] * (1.f / 1024.f) + 1e-5f);

    #pragma unroll
    for (int i = 0; i < 4; i++) {
        int n = tid + 256 * i;
        Y[(size_t)b * DD + n] = (v[i] - mu) * inv * gam[blk * DD + n] + bet[blk * DD + n];
    }
}

// ---------------- launch ----------------
extern "C" void kernel_launch(void* const* d_in, const int* in_sizes, int n_in,
                              void* d_out, int out_size)
{
    (void)in_sizes; (void)n_in; (void)out_size;
    const float* x  = (const float*)d_in[0];
    const float* gW = (const float*)d_in[1];
    const float* gb = (const float*)d_in[2];
    const float* qp = (const float*)d_in[3];
    const float* rW = (const float*)d_in[4];
    const float* rb = (const float*)d_in[5];
    const float* w2 = (const float*)d_in[6];
    const float* b2 = (const float*)d_in[7];
    const float* lg = (const float*)d_in[8];
    const float* lb = (const float*)d_in[9];
    float* out = (float*)d_out;

    cudaFuncSetAttribute(k_moe_gemm_mma, cudaFuncAttributeMaxDynamicSharedMemorySize, GEMM_SMEM);

    // one-time per launch: transpose + fp16-convert all expert w2 matrices (+ reset cnt)
    k_w2t<<<dim3(DD / 32, HHv / 32, 2 * EE), 256>>>(w2);

    for (int blk = 0; blk < 2; blk++) {
        k_gate_qsim_w<<<BB / 8, 256>>>(x, gW, gb, qp, blk);
        k_hidden<<<dim3(EE, (2 * BB) / HSLOTS), 256>>>(rW, rb, blk);
        dim3 g2(DD / BN, BB / BM, EE);
        k_moe_gemm_mma<<<g2, 256, GEMM_SMEM>>>(blk);
        k_ln<<<BB, 256>>>(x, b2, lg, lb, out, blk);
    }
}

// round 15
// speedup vs baseline: 2.5043x; 1.2128x over previous
#include <cuda_runtime.h>
#include <cuda_fp16.h>
#include <cstdint>
#include <math.h>

#define BB 8192
#define DD 1024
#define EE 8
#define NQv 8
#define NLv 2
#define HHv 1024

// ---------------- scratch (static device globals: no allocation) ----------------
__device__ float g_X1[(size_t)BB * DD];                 // inter-block activations
__device__ __half g_Hf[(size_t)BB * 2 * HHv];           // hidden, fp16
__device__ float g_Eout[(size_t)BB * 2 * DD];           // per-slot GEMM output
__device__ __half g_w2T[(size_t)2 * EE * DD * HHv];     // w2^T [e][n][k] fp16
__device__ float g_gWT[(size_t)2 * EE * DD];            // gate W transposed [blk][e][d]
__device__ float g_qv[(size_t)BB * 2 * NQv];            // per-slot Z expectations
__device__ int   g_cnt[EE];
__device__ int   g_list[EE * BB];                       // entries encode row*2+slot
__device__ int2   g_sel[BB];                            // per-row selected experts
__device__ float2 g_wgt[BB];                            // per-row gate weights

// ---------------- generic PTX helpers ----------------
static __device__ __forceinline__ uint32_t smem_u32(const void* p) {
    uint32_t a;
    asm("{ .reg .u64 t; cvta.to.shared.u64 t, %1; cvt.u32.u64 %0, t; }" : "=r"(a) : "l"(p));
    return a;
}
static __device__ __forceinline__ void cp16(uint32_t dst, const void* src) {
    asm volatile("cp.async.cg.shared.global [%0], [%1], 16;" :: "r"(dst), "l"(src) : "memory");
}
static __device__ __forceinline__ void cp16z(uint32_t dst, const void* src, int srcsize) {
    asm volatile("cp.async.cg.shared.global [%0], [%1], 16, %2;" :: "r"(dst), "l"(src), "r"(srcsize) : "memory");
}
static __device__ __forceinline__ void cp_commit() {
    asm volatile("cp.async.commit_group;" ::: "memory");
}
static __device__ __forceinline__ void ldm4(uint32_t* r, uint32_t addr) {
    asm volatile("ldmatrix.sync.aligned.m8n8.x4.shared.b16 {%0,%1,%2,%3}, [%4];"
        : "=r"(r[0]), "=r"(r[1]), "=r"(r[2]), "=r"(r[3]) : "r"(addr));
}
static __device__ __forceinline__ void mma16816(float* c, const uint32_t* a, const uint32_t* b) {
    asm volatile("mma.sync.aligned.m16n8k16.row.col.f32.f16.f16.f32 "
        "{%0,%1,%2,%3}, {%4,%5,%6,%7}, {%8,%9}, {%0,%1,%2,%3};"
        : "+f"(c[0]), "+f"(c[1]), "+f"(c[2]), "+f"(c[3])
        : "r"(a[0]), "r"(a[1]), "r"(a[2]), "r"(a[3]), "r"(b[0]), "r"(b[1]));
}

// ---------------- GEMM tile config (fp16 single-pass; BK=64, 3-stage ring) ----------------
#define BM 128
#define BN 128
#define BK 64
#define NCH (HHv / BK)                 // 16
#define RSTR 144                        // bytes per SMEM row (128 data + 16 pad; conflict-free)
#define TILE_BYT (BM * RSTR)            // 18432
#define STAGE_BYT (2 * TILE_BYT)        // 36864: A, B
#define NSTAGE 3
#define GEMM_SMEM (NSTAGE * STAGE_BYT)  // 110592

// ---------------- gate W transpose ----------------
__global__ __launch_bounds__(256) void k_gwt(const float* __restrict__ gW)
{
    int i = blockIdx.x * 256 + threadIdx.x;
    if (i < 2 * DD * EE) {
        int blk = i / (DD * EE);
        int r = i % (DD * EE);
        int d = r / EE, e = r % EE;
        g_gWT[(size_t)blk * EE * DD + (size_t)e * DD + d] = gW[i];
    }
}

// ---------------- w2 -> w2^T fp16 (+ reset cnt) ----------------
__global__ __launch_bounds__(256) void k_w2t(const float* __restrict__ w2)
{
    __shared__ float tile[32][33];
    int ez = blockIdx.z;
    int k0 = blockIdx.y * 32;
    int n0 = blockIdx.x * 32;
    int tx = threadIdx.x & 31, ty = threadIdx.x >> 5;

    if (blockIdx.x == 0 && blockIdx.y == 0 && blockIdx.z == 0 && threadIdx.x < EE)
        g_cnt[threadIdx.x] = 0;

    const float* src = w2 + (size_t)ez * HHv * DD;
    #pragma unroll
    for (int r = 0; r < 32; r += 8)
        tile[ty + r][tx] = src[(size_t)(k0 + ty + r) * DD + n0 + tx];
    __syncthreads();

    __half* dst = g_w2T + (size_t)ez * DD * HHv;
    #pragma unroll
    for (int r = 0; r < 32; r += 8) {
        float v = tile[tx][ty + r];
        dst[(size_t)(n0 + ty + r) * HHv + k0 + tx] = __float2half(v);
    }
}

// ---------------- warp-resident gate + qsim (1 warp per row; q vectors out) ----------------
__global__ __launch_bounds__(256) void k_gate_qsim_w(
    const float* __restrict__ Xext,
    const float* __restrict__ gb,
    const float* __restrict__ qp,
    int blk)
{
    __shared__ float2 stbuf[8][256];     // per-warp CNOT permute buffer
    const unsigned FULL = 0xffffffffu;
    int wid = threadIdx.x >> 5;
    int lane = threadIdx.x & 31;
    int b = blockIdx.x * 8 + wid;

    const float* X = (blk == 0) ? Xext : g_X1;
    const float4* xr4 = (const float4*)(X + (size_t)b * DD);

    float4 xv[8];
    #pragma unroll
    for (int j = 0; j < 8; j++) xv[j] = xr4[j * 32 + lane];

    // ---- gate logits (transposed gW: fully coalesced) ----
    float acc[EE];
    const float4* gT4 = (const float4*)(g_gWT + (size_t)blk * EE * DD);
    #pragma unroll
    for (int e = 0; e < EE; e++) {
        const float4* ge = gT4 + (size_t)e * (DD / 4);
        float a = 0.f;
        #pragma unroll
        for (int j = 0; j < 8; j++) {
            float4 g = ge[j * 32 + lane];
            a += xv[j].x * g.x + xv[j].y * g.y + xv[j].z * g.z + xv[j].w * g.w;
        }
        acc[e] = a;
    }
    #pragma unroll
    for (int e = 0; e < EE; e++) {
        #pragma unroll
        for (int o = 16; o > 0; o >>= 1) acc[e] += __shfl_xor_sync(FULL, acc[e], o);
    }

    // ---- softmax + top2 (redundant on all lanes) ----
    float l[EE], mx = -1e30f;
    #pragma unroll
    for (int e = 0; e < EE; e++) { l[e] = acc[e] + gb[blk * EE + e]; mx = fmaxf(mx, l[e]); }
    float sum = 0.f;
    #pragma unroll
    for (int e = 0; e < EE; e++) { l[e] = expf(l[e] - mx); sum += l[e]; }
    float inv = 1.f / sum;
    #pragma unroll
    for (int e = 0; e < EE; e++) l[e] *= inv;
    int i0 = 0;
    #pragma unroll
    for (int e = 1; e < EE; e++) if (l[e] > l[i0]) i0 = e;
    int i1 = (i0 == 0) ? 1 : 0;
    #pragma unroll
    for (int e = 0; e < EE; e++) if (e != i1 && e != i0 && l[e] > l[i1]) i1 = e;
    float p0 = l[i0], p1 = l[i1];
    float w1 = 1.f / (1.f + expf(p0 - p1));
    float w0 = 1.f - w1;
    if (lane == 0) {
        int pos0 = atomicAdd(&g_cnt[i0], 1); g_list[i0 * BB + pos0] = b * 2 + 0;
        int pos1 = atomicAdd(&g_cnt[i1], 1); g_list[i1 * BB + pos1] = b * 2 + 1;
        g_sel[b] = make_int2(i0, i1);
        g_wgt[b] = make_float2(w0, w1);
    }

    // ---- per-qubit angle cos/sin ----
    float v0 = __shfl_sync(FULL, xv[0].x, lane >> 2);
    float v1 = __shfl_sync(FULL, xv[0].y, lane >> 2);
    float v2 = __shfl_sync(FULL, xv[0].z, lane >> 2);
    float v3 = __shfl_sync(FULL, xv[0].w, lane >> 2);
    float xq = (lane & 2) ? ((lane & 1) ? v3 : v2) : ((lane & 1) ? v1 : v0);
    float cq_own, sq_own;
    sincosf(0.5f * xq, &sq_own, &cq_own);
    float cqv[NQv], sqv[NQv];
    #pragma unroll
    for (int q = 0; q < NQv; q++) {
        cqv[q] = __shfl_sync(FULL, cq_own, q);
        sqv[q] = __shfl_sync(FULL, sq_own, q);
    }

    int esel[2] = { i0, i1 };
    float2* sw = stbuf[wid];

    #pragma unroll
    for (int s = 0; s < 2; s++) {
        int e = esel[s];

        float2 st[8];
        #pragma unroll
        for (int j = 0; j < 8; j++) {
            int idx = lane * 8 + j;
            float v = 1.f;
            #pragma unroll
            for (int q = 0; q < NQv; q++)
                v *= ((idx >> (NQv - 1 - q)) & 1) ? sqv[q] : cqv[q];
            st[j] = make_float2(v, 0.f);
        }

        const float* qpe = qp + (size_t)(blk * EE + e) * NLv * NQv * 3;
        #pragma unroll
        for (int lyr = 0; lyr < NLv; lyr++) {
            const float* pp = qpe + (lyr * NQv + (lane & 7)) * 3;
            float phi = pp[0], th = pp[1], om = pp[2];
            float c, sn; sincosf(0.5f * th, &sn, &c);
            float sa, ca; sincosf(0.5f * (phi + om), &sa, &ca);
            float sb, cb; sincosf(0.5f * (phi - om), &sb, &cb);
            float o00r = ca * c,  o00i = -sa * c;
            float o11r = ca * c,  o11i =  sa * c;
            float o01r = -cb * sn, o01i = -sb * sn;
            float o10r =  cb * sn, o10i = -sb * sn;

            #pragma unroll
            for (int q = 0; q < NQv; q++) {
                float M00r = __shfl_sync(FULL, o00r, q), M00i = __shfl_sync(FULL, o00i, q);
                float M01r = __shfl_sync(FULL, o01r, q), M01i = __shfl_sync(FULL, o01i, q);
                float M10r = __shfl_sync(FULL, o10r, q), M10i = __shfl_sync(FULL, o10i, q);
                float M11r = __shfl_sync(FULL, o11r, q), M11i = __shfl_sync(FULL, o11i, q);
                const int pb = NQv - 1 - q;
                if (pb >= 3) {
                    int msk = 1 << (pb - 3);
                    int bit = (lane >> (pb - 3)) & 1;
                    float Msr = bit ? M11r : M00r, Msi = bit ? M11i : M00i;
                    float Mpr = bit ? M10r : M01r, Mpi = bit ? M10i : M01i;
                    #pragma unroll
                    for (int j = 0; j < 8; j++) {
                        float px = __shfl_xor_sync(FULL, st[j].x, msk);
                        float py = __shfl_xor_sync(FULL, st[j].y, msk);
                        float nx = Msr * st[j].x - Msi * st[j].y + Mpr * px - Mpi * py;
                        float ny = Msr * st[j].y + Msi * st[j].x + Mpr * py + Mpi * px;
                        st[j] = make_float2(nx, ny);
                    }
                } else {
                    const int m = 1 << pb;
                    #pragma unroll
                    for (int j = 0; j < 8; j++) {
                        if (!(j & m)) {
                            float2 a0 = st[j], a1 = st[j | m];
                            float2 n0, n1;
                            n0.x = M00r * a0.x - M00i * a0.y + M01r * a1.x - M01i * a1.y;
                            n0.y = M00r * a0.y + M00i * a0.x + M01r * a1.y + M01i * a1.x;
                            n1.x = M10r * a0.x - M10i * a0.y + M11r * a1.x - M11i * a1.y;
                            n1.y = M10r * a0.y + M10i * a0.x + M11r * a1.y + M11i * a1.x;
                            st[j] = n0; st[j | m] = n1;
                        }
                    }
                }
            }
            #pragma unroll
            for (int j = 0; j < 8; j++) sw[lane * 8 + j] = st[j];
            __syncwarp();
            #pragma unroll
            for (int j = 0; j < 8; j++) {
                int idx = lane * 8 + j;
                int jsrc = idx;
                #pragma unroll
                for (int q = NQv - 2; q >= 0; q--) {
                    int pc = NQv - 1 - q, pt = NQv - 2 - q;
                    jsrc ^= ((jsrc >> pc) & 1) << pt;
                }
                st[j] = sw[jsrc];
            }
            __syncwarp();
        }

        // ---- Z expectations -> g_qv ----
        float zp[NQv];
        #pragma unroll
        for (int k = 0; k < NQv; k++) zp[k] = 0.f;
        #pragma unroll
        for (int j = 0; j < 8; j++) {
            int idx = lane * 8 + j;
            float p = st[j].x * st[j].x + st[j].y * st[j].y;
            #pragma unroll
            for (int k = 0; k < NQv; k++)
                zp[k] += ((idx >> (NQv - 1 - k)) & 1) ? -p : p;
        }
        #pragma unroll
        for (int k = 0; k < NQv; k++) {
            #pragma unroll
            for (int o = 16; o > 0; o >>= 1) zp[k] += __shfl_xor_sync(FULL, zp[k], o);
        }
        if (lane == 0) {
            size_t slot = (size_t)b * 2 + s;
            *(float4*)(g_qv + slot * NQv)     = make_float4(zp[0], zp[1], zp[2], zp[3]);
            *(float4*)(g_qv + slot * NQv + 4) = make_float4(zp[4], zp[5], zp[6], zp[7]);
        }
    }
}

// ---------------- grouped hidden layer: rW in SMEM, per-expert slot lists ----------------
#define HSLOTS 128
__global__ __launch_bounds__(256) void k_hidden(
    const float* __restrict__ rW, const float* __restrict__ rb, int blk)
{
    __shared__ float s_rW[NQv * HHv];   // 32KB
    __shared__ float s_rb[HHv];         // 4KB

    int e = blockIdx.x;
    int tile = blockIdx.y;
    int n_e = g_cnt[e];
    if (tile * HSLOTS >= n_e) return;

    int t = threadIdx.x;

    const float4* src = (const float4*)(rW + (size_t)(blk * EE + e) * NQv * HHv);
    float4* dst = (float4*)s_rW;
    #pragma unroll
    for (int i = 0; i < 8; i++) dst[t + 256 * i] = src[t + 256 * i];
    ((float4*)s_rb)[t] = ((const float4*)(rb + (size_t)(blk * EE + e) * HHv))[t];
    __syncthreads();

    float4 rbv = ((const float4*)s_rb)[t];
    const float4* w4[NQv];
    #pragma unroll
    for (int j = 0; j < NQv; j++) w4[j] = (const float4*)(s_rW + j * HHv);

    int hi_end = min(n_e, (tile + 1) * HSLOTS);
    for (int idx = tile * HSLOTS; idx < hi_end; idx++) {
        int entry = g_list[e * BB + idx];
        float2 wpair = g_wgt[entry >> 1];
        float wgt = (entry & 1) ? wpair.y : wpair.x;
        const float* q = g_qv + (size_t)entry * NQv;
        float qr[NQv];
        #pragma unroll
        for (int j = 0; j < NQv; j++) qr[j] = __ldg(q + j);

        float4 a = rbv;
        #pragma unroll
        for (int j = 0; j < NQv; j++) {
            float4 wv = w4[j][t];
            a.x += qr[j] * wv.x; a.y += qr[j] * wv.y;
            a.z += qr[j] * wv.z; a.w += qr[j] * wv.w;
        }
        a.x = fmaxf(a.x, 0.f) * wgt; a.y = fmaxf(a.y, 0.f) * wgt;
        a.z = fmaxf(a.z, 0.f) * wgt; a.w = fmaxf(a.w, 0.f) * wgt;

        __half hx = __float2half(a.x), hy = __float2half(a.y);
        __half hz = __float2half(a.z), hw = __float2half(a.w);
        uint2 uh;
        uh.x = ((uint32_t)__half_as_ushort(hy) << 16) | __half_as_ushort(hx);
        uh.y = ((uint32_t)__half_as_ushort(hw) << 16) | __half_as_ushort(hz);
        ((uint2*)(g_Hf + (size_t)entry * HHv))[t] = uh;
    }
}

// ---------------- grouped expert GEMM via mma.sync (fp16, BK=64, 3-stage) ----------------
__global__ __launch_bounds__(256, 2) void k_moe_gemm_mma(int blk)
{
    extern __shared__ char dsm[];
    __shared__ int rows[BM];

    int e = blockIdx.z;
    int n_e = g_cnt[e];
    int m0 = blockIdx.y * BM;
    if (m0 >= n_e) return;
    int n0 = blockIdx.x * BN;

    int tid = threadIdx.x;
    int lane = tid & 31;
    int wid = tid >> 5;
    int warp_m = wid >> 2;
    int warp_n = wid & 3;

    if (tid < BM) {
        int m = m0 + tid;
        rows[tid] = (m < n_e) ? g_list[e * BB + m] : -1;
    }
    __syncthreads();

    uint32_t sbase = smem_u32(dsm);
    const __half* Bp = g_w2T + (size_t)(blk * EE + e) * DD * HHv;

    auto load_stage = [&](int chunk, int stage) {
        uint32_t sb = sbase + stage * STAGE_BYT;
        int kofs = chunk * BK;
        #pragma unroll
        for (int j = 0; j < 4; j++) {
            int idx = tid + 256 * j;       // 0..1023
            int row = idx >> 3;
            int seg = idx & 7;
            uint32_t doff = (uint32_t)(row * RSTR + seg * 16);
            int slot = rows[row];
            int sz = (slot >= 0) ? 16 : 0;
            size_t off = (size_t)(slot >= 0 ? slot : 0) * HHv + kofs + seg * 8;
            cp16z(sb + 0 * TILE_BYT + doff, g_Hf + off, sz);
            size_t boff = (size_t)(n0 + row) * HHv + kofs + seg * 8;
            cp16(sb + 1 * TILE_BYT + doff, Bp + boff);
        }
    };

    float acc[4][4][4];
    #pragma unroll
    for (int i = 0; i < 4; i++)
        #pragma unroll
        for (int j = 0; j < 4; j++)
            #pragma unroll
            for (int q = 0; q < 4; q++) acc[i][j][q] = 0.f;

    uint32_t a_row = (uint32_t)(warp_m * 64 + (lane & 15));
    uint32_t a_colp = (uint32_t)((lane >> 4) * 16);
    uint32_t b_row = (uint32_t)(warp_n * 32 + (lane & 7) + ((lane >> 4) & 1) * 8);
    uint32_t b_colp = (uint32_t)(((lane >> 3) & 1) * 16);

    load_stage(0, 0); cp_commit();
    load_stage(1, 1); cp_commit();

    for (int i = 0; i < NCH; i++) {
        if (i + 1 < NCH) asm volatile("cp.async.wait_group 1;" ::: "memory");
        else             asm volatile("cp.async.wait_group 0;" ::: "memory");
        __syncthreads();
        int nx = i + 2;
        if (nx < NCH) { load_stage(nx, nx % NSTAGE); cp_commit(); }

        uint32_t sb = sbase + (i % NSTAGE) * STAGE_BYT;
        uint32_t sA = sb, sB = sb + TILE_BYT;

        #pragma unroll
        for (int kk = 0; kk < BK / 16; kk++) {
            uint32_t kbyte = (uint32_t)(kk * 32);
            uint32_t ah[4][4], bh[2][4];

            #pragma unroll
            for (int mg = 0; mg < 4; mg++)
                ldm4(ah[mg], sA + (a_row + mg * 16) * RSTR + kbyte + a_colp);
            #pragma unroll
            for (int ng = 0; ng < 2; ng++)
                ldm4(bh[ng], sB + (b_row + ng * 16) * RSTR + kbyte + b_colp);

            #pragma unroll
            for (int mg = 0; mg < 4; mg++)
                #pragma unroll
                for (int nf = 0; nf < 4; nf++)
                    mma16816(acc[mg][nf], ah[mg], &bh[nf >> 1][(nf & 1) * 2]);
        }
    }

    int mb = warp_m * 64 + (lane >> 2);
    int nb = n0 + warp_n * 32 + (lane & 3) * 2;
    #pragma unroll
    for (int mg = 0; mg < 4; mg++) {
        int r0 = mb + mg * 16;
        int r1 = r0 + 8;
        int s0 = rows[r0], s1 = rows[r1];
        #pragma unroll
        for (int nf = 0; nf < 4; nf++) {
            int n = nb + nf * 8;
            if (s0 >= 0) *(float2*)(g_Eout + (size_t)s0 * DD + n) = make_float2(acc[mg][nf][0], acc[mg][nf][1]);
            if (s1 >= 0) *(float2*)(g_Eout + (size_t)s1 * DD + n) = make_float2(acc[mg][nf][2], acc[mg][nf][3]);
        }
    }
}

// ---------------- layernorm (residual + bias + both slot outputs) ----------------
__device__ __forceinline__ float blockReduceSum(float v, float* red)
{
    __syncthreads();
    int lane = threadIdx.x & 31;
    int w = threadIdx.x >> 5;
    #pragma unroll
    for (int o = 16; o > 0; o >>= 1) v += __shfl_xor_sync(0xffffffffu, v, o);
    if (lane == 0) red[w] = v;
    __syncthreads();
    float r = (lane < 8) ? red[lane] : 0.f;
    #pragma unroll
    for (int o = 4; o > 0; o >>= 1) r += __shfl_xor_sync(0xffffffffu, r, o);
    return r;
}

__global__ __launch_bounds__(256) void k_ln(
    const float* __restrict__ Xext, const float* __restrict__ b2,
    const float* __restrict__ gam, const float* __restrict__ bet,
    float* __restrict__ Yext, int blk)
{
    __shared__ float red[32];
    __shared__ float bc[2];
    int b = blockIdx.x, tid = threadIdx.x;
    float* Y = (blk == 0) ? g_X1 : Yext;
    const float* xrow = ((blk == 0) ? Xext : g_X1) + (size_t)b * DD;

    if (blk == 0 && blockIdx.x == 0 && tid < EE) g_cnt[tid] = 0;  // reset for next block

    int2 se = g_sel[b];
    float2 wv = g_wgt[b];
    const float* b2a = b2 + ((size_t)blk * EE + se.x) * DD;
    const float* b2b = b2 + ((size_t)blk * EE + se.y) * DD;
    const float* e0 = g_Eout + (size_t)(2 * b) * DD;
    const float* e1 = e0 + DD;

    float v[4];
    float s = 0.f;
    #pragma unroll
    for (int i = 0; i < 4; i++) {
        int n = tid + 256 * i;
        v[i] = xrow[n] + wv.x * b2a[n] + wv.y * b2b[n] + e0[n] + e1[n];
        s += v[i];
    }
    float tot = blockReduceSum(s, red);
    if (tid == 0) bc[0] = tot;
    __syncthreads();
    float mu = bc[0] * (1.f / 1024.f);

    float s2 = 0.f;
    #pragma unroll
    for (int i = 0; i < 4; i++) { float d = v[i] - mu; s2 += d * d; }
    float tot2 = blockReduceSum(s2, red);
    if (tid == 0) bc[1] = tot2;
    __syncthreads();
    float inv = 1.f / sqrtf(bc[1] * (1.f / 1024.f) + 1e-5f);

    #pragma unroll
    for (int i = 0; i < 4; i++) {
        int n = tid + 256 * i;
        Y[(size_t)b * DD + n] = (v[i] - mu) * inv * gam[blk * DD + n] + bet[blk * DD + n];
    }
}

// ---------------- launch ----------------
extern "C" void kernel_launch(void* const* d_in, const int* in_sizes, int n_in,
                              void* d_out, int out_size)
{
    (void)in_sizes; (void)n_in; (void)out_size;
    const float* x  = (const float*)d_in[0];
    const float* gW = (const float*)d_in[1];
    const float* gb = (const float*)d_in[2];
    const float* qp = (const float*)d_in[3];
    const float* rW = (const float*)d_in[4];
    const float* rb = (const float*)d_in[5];
    const float* w2 = (const float*)d_in[6];
    const float* b2 = (const float*)d_in[7];
    const float* lg = (const float*)d_in[8];
    const float* lb = (const float*)d_in[9];
    float* out = (float*)d_out;

    cudaFuncSetAttribute(k_moe_gemm_mma, cudaFuncAttributeMaxDynamicSharedMemorySize, GEMM_SMEM);

    // one-time per launch: transposes + fp16-convert w2 (+ reset cnt)
    k_gwt<<<(2 * DD * EE + 255) / 256, 256>>>(gW);
    k_w2t<<<dim3(DD / 32, HHv / 32, 2 * EE), 256>>>(w2);

    for (int blk = 0; blk < 2; blk++) {
        k_gate_qsim_w<<<BB / 8, 256>>>(x, gb, qp, blk);
        k_hidden<<<dim3(EE, (2 * BB) / HSLOTS), 256>>>(rW, rb, blk);
        dim3 g2(DD / BN, BB / BM, EE);
        k_moe_gemm_mma<<<g2, 256, GEMM_SMEM>>>(blk);
        k_ln<<<BB, 256>>>(x, b2, lg, lb, out, blk);
    }
}

// round 16
// speedup vs baseline: 2.8159x; 1.1245x over previous
#include <cuda_runtime.h>
#include <cuda_fp16.h>
#include <cstdint>
#include <math.h>

#define BB 8192
#define DD 1024
#define EE 8
#define NQv 8
#define NLv 2
#define HHv 1024

// ---------------- scratch (static device globals: no allocation) ----------------
__device__ float g_X1[(size_t)BB * DD];                 // inter-block activations
__device__ __half g_Hf[(size_t)BB * 2 * HHv];           // hidden, fp16
__device__ float g_Eout[(size_t)BB * 2 * DD];           // per-slot GEMM output
__device__ __half g_w2T[(size_t)2 * EE * DD * HHv];     // w2^T [e][n][k] fp16
__device__ float g_gWT[(size_t)2 * EE * DD];            // gate W transposed [blk][e][d]
__device__ float g_qv[(size_t)BB * 2 * NQv];            // per-slot Z expectations
__device__ int   g_cnt[EE];
__device__ int   g_list[EE * BB];                       // entries encode row*2+slot
__device__ int2   g_sel[BB];                            // per-row selected experts
__device__ float2 g_wgt[BB];                            // per-row gate weights

// ---------------- generic PTX helpers ----------------
static __device__ __forceinline__ uint32_t smem_u32(const void* p) {
    uint32_t a;
    asm("{ .reg .u64 t; cvta.to.shared.u64 t, %1; cvt.u32.u64 %0, t; }" : "=r"(a) : "l"(p));
    return a;
}
static __device__ __forceinline__ void cp16(uint32_t dst, const void* src) {
    asm volatile("cp.async.cg.shared.global [%0], [%1], 16;" :: "r"(dst), "l"(src) : "memory");
}
static __device__ __forceinline__ void cp16z(uint32_t dst, const void* src, int srcsize) {
    asm volatile("cp.async.cg.shared.global [%0], [%1], 16, %2;" :: "r"(dst), "l"(src), "r"(srcsize) : "memory");
}
static __device__ __forceinline__ void cp_commit() {
    asm volatile("cp.async.commit_group;" ::: "memory");
}
static __device__ __forceinline__ void ldm4(uint32_t* r, uint32_t addr) {
    asm volatile("ldmatrix.sync.aligned.m8n8.x4.shared.b16 {%0,%1,%2,%3}, [%4];"
        : "=r"(r[0]), "=r"(r[1]), "=r"(r[2]), "=r"(r[3]) : "r"(addr));
}
static __device__ __forceinline__ void mma16816(float* c, const uint32_t* a, const uint32_t* b) {
    asm volatile("mma.sync.aligned.m16n8k16.row.col.f32.f16.f16.f32 "
        "{%0,%1,%2,%3}, {%4,%5,%6,%7}, {%8,%9}, {%0,%1,%2,%3};"
        : "+f"(c[0]), "+f"(c[1]), "+f"(c[2]), "+f"(c[3])
        : "r"(a[0]), "r"(a[1]), "r"(a[2]), "r"(a[3]), "r"(b[0]), "r"(b[1]));
}

// ---------------- GEMM tile config (fp16 single-pass; BK=64, 3-stage ring) ----------------
#define BM 128
#define BN 128
#define BK 64
#define NCH (HHv / BK)                 // 16
#define RSTR 144                        // bytes per SMEM row (128 data + 16 pad; conflict-free)
#define TILE_BYT (BM * RSTR)            // 18432
#define STAGE_BYT (2 * TILE_BYT)        // 36864: A, B
#define NSTAGE 3
#define GEMM_SMEM (NSTAGE * STAGE_BYT)  // 110592

// ---------------- gate W transpose ----------------
__global__ __launch_bounds__(256) void k_gwt(const float* __restrict__ gW)
{
    int i = blockIdx.x * 256 + threadIdx.x;
    if (i < 2 * DD * EE) {
        int blk = i / (DD * EE);
        int r = i % (DD * EE);
        int d = r / EE, e = r % EE;
        g_gWT[(size_t)blk * EE * DD + (size_t)e * DD + d] = gW[i];
    }
}

// ---------------- w2 -> w2^T fp16 (+ reset cnt) ----------------
__global__ __launch_bounds__(256) void k_w2t(const float* __restrict__ w2)
{
    __shared__ float tile[32][33];
    int ez = blockIdx.z;
    int k0 = blockIdx.y * 32;
    int n0 = blockIdx.x * 32;
    int tx = threadIdx.x & 31, ty = threadIdx.x >> 5;

    if (blockIdx.x == 0 && blockIdx.y == 0 && blockIdx.z == 0 && threadIdx.x < EE)
        g_cnt[threadIdx.x] = 0;

    const float* src = w2 + (size_t)ez * HHv * DD;
    #pragma unroll
    for (int r = 0; r < 32; r += 8)
        tile[ty + r][tx] = src[(size_t)(k0 + ty + r) * DD + n0 + tx];
    __syncthreads();

    __half* dst = g_w2T + (size_t)ez * DD * HHv;
    #pragma unroll
    for (int r = 0; r < 32; r += 8) {
        float v = tile[tx][ty + r];
        dst[(size_t)(n0 + ty + r) * HHv + k0 + tx] = __float2half(v);
    }
}

// ---------------- warp-resident gate + qsim (1 warp per row; q vectors out) ----------------
__global__ __launch_bounds__(256) void k_gate_qsim_w(
    const float* __restrict__ Xext,
    const float* __restrict__ gb,
    const float* __restrict__ qp,
    int blk)
{
    __shared__ float2 stbuf[8][256];     // per-warp CNOT permute buffer
    const unsigned FULL = 0xffffffffu;
    int wid = threadIdx.x >> 5;
    int lane = threadIdx.x & 31;
    int b = blockIdx.x * 8 + wid;

    const float* X = (blk == 0) ? Xext : g_X1;
    const float4* xr4 = (const float4*)(X + (size_t)b * DD);

    float4 xv[8];
    #pragma unroll
    for (int j = 0; j < 8; j++) xv[j] = xr4[j * 32 + lane];

    // ---- gate logits (transposed gW: fully coalesced) ----
    float acc[EE];
    const float4* gT4 = (const float4*)(g_gWT + (size_t)blk * EE * DD);
    #pragma unroll
    for (int e = 0; e < EE; e++) {
        const float4* ge = gT4 + (size_t)e * (DD / 4);
        float a = 0.f;
        #pragma unroll
        for (int j = 0; j < 8; j++) {
            float4 g = ge[j * 32 + lane];
            a += xv[j].x * g.x + xv[j].y * g.y + xv[j].z * g.z + xv[j].w * g.w;
        }
        acc[e] = a;
    }
    #pragma unroll
    for (int e = 0; e < EE; e++) {
        #pragma unroll
        for (int o = 16; o > 0; o >>= 1) acc[e] += __shfl_xor_sync(FULL, acc[e], o);
    }

    // ---- softmax + top2 (redundant on all lanes) ----
    float l[EE], mx = -1e30f;
    #pragma unroll
    for (int e = 0; e < EE; e++) { l[e] = acc[e] + gb[blk * EE + e]; mx = fmaxf(mx, l[e]); }
    float sum = 0.f;
    #pragma unroll
    for (int e = 0; e < EE; e++) { l[e] = expf(l[e] - mx); sum += l[e]; }
    float inv = 1.f / sum;
    #pragma unroll
    for (int e = 0; e < EE; e++) l[e] *= inv;
    int i0 = 0;
    #pragma unroll
    for (int e = 1; e < EE; e++) if (l[e] > l[i0]) i0 = e;
    int i1 = (i0 == 0) ? 1 : 0;
    #pragma unroll
    for (int e = 0; e < EE; e++) if (e != i1 && e != i0 && l[e] > l[i1]) i1 = e;
    float p0 = l[i0], p1 = l[i1];
    float w1 = 1.f / (1.f + expf(p0 - p1));
    float w0 = 1.f - w1;
    if (lane == 0) {
        int pos0 = atomicAdd(&g_cnt[i0], 1); g_list[i0 * BB + pos0] = b * 2 + 0;
        int pos1 = atomicAdd(&g_cnt[i1], 1); g_list[i1 * BB + pos1] = b * 2 + 1;
        g_sel[b] = make_int2(i0, i1);
        g_wgt[b] = make_float2(w0, w1);
    }

    // ---- per-qubit angle cos/sin ----
    float v0 = __shfl_sync(FULL, xv[0].x, lane >> 2);
    float v1 = __shfl_sync(FULL, xv[0].y, lane >> 2);
    float v2 = __shfl_sync(FULL, xv[0].z, lane >> 2);
    float v3 = __shfl_sync(FULL, xv[0].w, lane >> 2);
    float xq = (lane & 2) ? ((lane & 1) ? v3 : v2) : ((lane & 1) ? v1 : v0);
    float cq_own, sq_own;
    sincosf(0.5f * xq, &sq_own, &cq_own);
    float cqv[NQv], sqv[NQv];
    #pragma unroll
    for (int q = 0; q < NQv; q++) {
        cqv[q] = __shfl_sync(FULL, cq_own, q);
        sqv[q] = __shfl_sync(FULL, sq_own, q);
    }

    int esel[2] = { i0, i1 };
    float2* sw = stbuf[wid];

    #pragma unroll
    for (int s = 0; s < 2; s++) {
        int e = esel[s];

        float2 st[8];
        #pragma unroll
        for (int j = 0; j < 8; j++) {
            int idx = lane * 8 + j;
            float v = 1.f;
            #pragma unroll
            for (int q = 0; q < NQv; q++)
                v *= ((idx >> (NQv - 1 - q)) & 1) ? sqv[q] : cqv[q];
            st[j] = make_float2(v, 0.f);
        }

        const float* qpe = qp + (size_t)(blk * EE + e) * NLv * NQv * 3;
        #pragma unroll
        for (int lyr = 0; lyr < NLv; lyr++) {
            const float* pp = qpe + (lyr * NQv + (lane & 7)) * 3;
            float phi = pp[0], th = pp[1], om = pp[2];
            float c, sn; sincosf(0.5f * th, &sn, &c);
            float sa, ca; sincosf(0.5f * (phi + om), &sa, &ca);
            float sb, cb; sincosf(0.5f * (phi - om), &sb, &cb);
            float o00r = ca * c,  o00i = -sa * c;
            float o11r = ca * c,  o11i =  sa * c;
            float o01r = -cb * sn, o01i = -sb * sn;
            float o10r =  cb * sn, o10i = -sb * sn;

            #pragma unroll
            for (int q = 0; q < NQv; q++) {
                float M00r = __shfl_sync(FULL, o00r, q), M00i = __shfl_sync(FULL, o00i, q);
                float M01r = __shfl_sync(FULL, o01r, q), M01i = __shfl_sync(FULL, o01i, q);
                float M10r = __shfl_sync(FULL, o10r, q), M10i = __shfl_sync(FULL, o10i, q);
                float M11r = __shfl_sync(FULL, o11r, q), M11i = __shfl_sync(FULL, o11i, q);
                const int pb = NQv - 1 - q;
                if (pb >= 3) {
                    int msk = 1 << (pb - 3);
                    int bit = (lane >> (pb - 3)) & 1;
                    float Msr = bit ? M11r : M00r, Msi = bit ? M11i : M00i;
                    float Mpr = bit ? M10r : M01r, Mpi = bit ? M10i : M01i;
                    #pragma unroll
                    for (int j = 0; j < 8; j++) {
                        float px = __shfl_xor_sync(FULL, st[j].x, msk);
                        float py = __shfl_xor_sync(FULL, st[j].y, msk);
                        float nx = Msr * st[j].x - Msi * st[j].y + Mpr * px - Mpi * py;
                        float ny = Msr * st[j].y + Msi * st[j].x + Mpr * py + Mpi * px;
                        st[j] = make_float2(nx, ny);
                    }
                } else {
                    const int m = 1 << pb;
                    #pragma unroll
                    for (int j = 0; j < 8; j++) {
                        if (!(j & m)) {
                            float2 a0 = st[j], a1 = st[j | m];
                            float2 n0, n1;
                            n0.x = M00r * a0.x - M00i * a0.y + M01r * a1.x - M01i * a1.y;
                            n0.y = M00r * a0.y + M00i * a0.x + M01r * a1.y + M01i * a1.x;
                            n1.x = M10r * a0.x - M10i * a0.y + M11r * a1.x - M11i * a1.y;
                            n1.y = M10r * a0.y + M10i * a0.x + M11r * a1.y + M11i * a1.x;
                            st[j] = n0; st[j | m] = n1;
                        }
                    }
                }
            }
            #pragma unroll
            for (int j = 0; j < 8; j++) sw[lane * 8 + j] = st[j];
            __syncwarp();
            #pragma unroll
            for (int j = 0; j < 8; j++) {
                int idx = lane * 8 + j;
                int jsrc = idx;
                #pragma unroll
                for (int q = NQv - 2; q >= 0; q--) {
                    int pc = NQv - 1 - q, pt = NQv - 2 - q;
                    jsrc ^= ((jsrc >> pc) & 1) << pt;
                }
                st[j] = sw[jsrc];
            }
            __syncwarp();
        }

        // ---- Z expectations -> g_qv ----
        float zp[NQv];
        #pragma unroll
        for (int k = 0; k < NQv; k++) zp[k] = 0.f;
        #pragma unroll
        for (int j = 0; j < 8; j++) {
            int idx = lane * 8 + j;
            float p = st[j].x * st[j].x + st[j].y * st[j].y;
            #pragma unroll
            for (int k = 0; k < NQv; k++)
                zp[k] += ((idx >> (NQv - 1 - k)) & 1) ? -p : p;
        }
        #pragma unroll
        for (int k = 0; k < NQv; k++) {
            #pragma unroll
            for (int o = 16; o > 0; o >>= 1) zp[k] += __shfl_xor_sync(FULL, zp[k], o);
        }
        if (lane == 0) {
            size_t slot = (size_t)b * 2 + s;
            *(float4*)(g_qv + slot * NQv)     = make_float4(zp[0], zp[1], zp[2], zp[3]);
            *(float4*)(g_qv + slot * NQv + 4) = make_float4(zp[4], zp[5], zp[6], zp[7]);
        }
    }
}

// ---------------- grouped hidden layer: warp-per-slot, rW in SMEM ----------------
#define HSLOTS 64
__global__ __launch_bounds__(256) void k_hidden(
    const float* __restrict__ rW, const float* __restrict__ rb, int blk)
{
    __shared__ float s_rW[NQv * HHv];   // 32KB
    __shared__ float s_rb[HHv];         // 4KB

    int e = blockIdx.x;
    int tile = blockIdx.y;
    int n_e = g_cnt[e];
    if (tile * HSLOTS >= n_e) return;

    int t = threadIdx.x;
    int lane = t & 31;
    int wid = t >> 5;

    // stage rW + rb (cooperative, coalesced)
    const float4* src = (const float4*)(rW + (size_t)(blk * EE + e) * NQv * HHv);
    float4* dst = (float4*)s_rW;
    #pragma unroll
    for (int i = 0; i < 8; i++) dst[t + 256 * i] = src[t + 256 * i];
    ((float4*)s_rb)[t] = ((const float4*)(rb + (size_t)(blk * EE + e) * HHv))[t];
    __syncthreads();

    int hi_end = min(n_e, (tile + 1) * HSLOTS);

    // warp-per-slot: each warp processes its own slot stream (8 in flight per CTA)
    for (int idx = tile * HSLOTS + wid; idx < hi_end; idx += 8) {
        int entry = g_list[e * BB + idx];
        float2 wpair = g_wgt[entry >> 1];
        float wgt = (entry & 1) ? wpair.y : wpair.x;
        const float4* qv4 = (const float4*)(g_qv + (size_t)entry * NQv);
        float4 q0 = __ldg(qv4), q1 = __ldg(qv4 + 1);
        float qr[NQv] = { q0.x, q0.y, q0.z, q0.w, q1.x, q1.y, q1.z, q1.w };

        uint2* dhf = (uint2*)(g_Hf + (size_t)entry * HHv);
        #pragma unroll
        for (int j = 0; j < 8; j++) {
            int g = j * 32 + lane;
            float4 a = ((const float4*)s_rb)[g];
            #pragma unroll
            for (int jj = 0; jj < NQv; jj++) {
                float4 wv = ((const float4*)(s_rW + jj * HHv))[g];
                a.x += qr[jj] * wv.x; a.y += qr[jj] * wv.y;
                a.z += qr[jj] * wv.z; a.w += qr[jj] * wv.w;
            }
            a.x = fmaxf(a.x, 0.f) * wgt; a.y = fmaxf(a.y, 0.f) * wgt;
            a.z = fmaxf(a.z, 0.f) * wgt; a.w = fmaxf(a.w, 0.f) * wgt;

            __half hx = __float2half(a.x), hy = __float2half(a.y);
            __half hz = __float2half(a.z), hw = __float2half(a.w);
            uint2 uh;
            uh.x = ((uint32_t)__half_as_ushort(hy) << 16) | __half_as_ushort(hx);
            uh.y = ((uint32_t)__half_as_ushort(hw) << 16) | __half_as_ushort(hz);
            dhf[g] = uh;
        }
    }
}

// ---------------- grouped expert GEMM via mma.sync (fp16, BK=64, 3-stage) ----------------
__global__ __launch_bounds__(256, 2) void k_moe_gemm_mma(int blk)
{
    extern __shared__ char dsm[];
    __shared__ int rows[BM];

    int e = blockIdx.z;
    int n_e = g_cnt[e];
    int m0 = blockIdx.y * BM;
    if (m0 >= n_e) return;
    int n0 = blockIdx.x * BN;

    int tid = threadIdx.x;
    int lane = tid & 31;
    int wid = tid >> 5;
    int warp_m = wid >> 2;
    int warp_n = wid & 3;

    if (tid < BM) {
        int m = m0 + tid;
        rows[tid] = (m < n_e) ? g_list[e * BB + m] : -1;
    }
    __syncthreads();

    uint32_t sbase = smem_u32(dsm);
    const __half* Bp = g_w2T + (size_t)(blk * EE + e) * DD * HHv;

    auto load_stage = [&](int chunk, int stage) {
        uint32_t sb = sbase + stage * STAGE_BYT;
        int kofs = chunk * BK;
        #pragma unroll
        for (int j = 0; j < 4; j++) {
            int idx = tid + 256 * j;       // 0..1023
            int row = idx >> 3;
            int seg = idx & 7;
            uint32_t doff = (uint32_t)(row * RSTR + seg * 16);
            int slot = rows[row];
            int sz = (slot >= 0) ? 16 : 0;
            size_t off = (size_t)(slot >= 0 ? slot : 0) * HHv + kofs + seg * 8;
            cp16z(sb + 0 * TILE_BYT + doff, g_Hf + off, sz);
            size_t boff = (size_t)(n0 + row) * HHv + kofs + seg * 8;
            cp16(sb + 1 * TILE_BYT + doff, Bp + boff);
        }
    };

    float acc[4][4][4];
    #pragma unroll
    for (int i = 0; i < 4; i++)
        #pragma unroll
        for (int j = 0; j < 4; j++)
            #pragma unroll
            for (int q = 0; q < 4; q++) acc[i][j][q] = 0.f;

    uint32_t a_row = (uint32_t)(warp_m * 64 + (lane & 15));
    uint32_t a_colp = (uint32_t)((lane >> 4) * 16);
    uint32_t b_row = (uint32_t)(warp_n * 32 + (lane & 7) + ((lane >> 4) & 1) * 8);
    uint32_t b_colp = (uint32_t)(((lane >> 3) & 1) * 16);

    load_stage(0, 0); cp_commit();
    load_stage(1, 1); cp_commit();

    for (int i = 0; i < NCH; i++) {
        if (i + 1 < NCH) asm volatile("cp.async.wait_group 1;" ::: "memory");
        else             asm volatile("cp.async.wait_group 0;" ::: "memory");
        __syncthreads();
        int nx = i + 2;
        if (nx < NCH) { load_stage(nx, nx % NSTAGE); cp_commit(); }

        uint32_t sb = sbase + (i % NSTAGE) * STAGE_BYT;
        uint32_t sA = sb, sB = sb + TILE_BYT;

        #pragma unroll
        for (int kk = 0; kk < BK / 16; kk++) {
            uint32_t kbyte = (uint32_t)(kk * 32);
            uint32_t ah[4][4], bh[2][4];

            #pragma unroll
            for (int mg = 0; mg < 4; mg++)
                ldm4(ah[mg], sA + (a_row + mg * 16) * RSTR + kbyte + a_colp);
            #pragma unroll
            for (int ng = 0; ng < 2; ng++)
                ldm4(bh[ng], sB + (b_row + ng * 16) * RSTR + kbyte + b_colp);

            #pragma unroll
            for (int mg = 0; mg < 4; mg++)
                #pragma unroll
                for (int nf = 0; nf < 4; nf++)
                    mma16816(acc[mg][nf], ah[mg], &bh[nf >> 1][(nf & 1) * 2]);
        }
    }

    int mb = warp_m * 64 + (lane >> 2);
    int nb = n0 + warp_n * 32 + (lane & 3) * 2;
    #pragma unroll
    for (int mg = 0; mg < 4; mg++) {
        int r0 = mb + mg * 16;
        int r1 = r0 + 8;
        int s0 = rows[r0], s1 = rows[r1];
        #pragma unroll
        for (int nf = 0; nf < 4; nf++) {
            int n = nb + nf * 8;
            if (s0 >= 0) *(float2*)(g_Eout + (size_t)s0 * DD + n) = make_float2(acc[mg][nf][0], acc[mg][nf][1]);
            if (s1 >= 0) *(float2*)(g_Eout + (size_t)s1 * DD + n) = make_float2(acc[mg][nf][2], acc[mg][nf][3]);
        }
    }
}

// ---------------- layernorm (residual + bias + both slot outputs) ----------------
__device__ __forceinline__ float blockReduceSum(float v, float* red)
{
    __syncthreads();
    int lane = threadIdx.x & 31;
    int w = threadIdx.x >> 5;
    #pragma unroll
    for (int o = 16; o > 0; o >>= 1) v += __shfl_xor_sync(0xffffffffu, v, o);
    if (lane == 0) red[w] = v;
    __syncthreads();
    float r = (lane < 8) ? red[lane] : 0.f;
    #pragma unroll
    for (int o = 4; o > 0; o >>= 1) r += __shfl_xor_sync(0xffffffffu, r, o);
    return r;
}

__global__ __launch_bounds__(256) void k_ln(
    const float* __restrict__ Xext, const float* __restrict__ b2,
    const float* __restrict__ gam, const float* __restrict__ bet,
    float* __restrict__ Yext, int blk)
{
    __shared__ float red[32];
    __shared__ float bc[2];
    int b = blockIdx.x, tid = threadIdx.x;
    float* Y = (blk == 0) ? g_X1 : Yext;
    const float* xrow = ((blk == 0) ? Xext : g_X1) + (size_t)b * DD;

    if (blk == 0 && blockIdx.x == 0 && tid < EE) g_cnt[tid] = 0;  // reset for next block

    int2 se = g_sel[b];
    float2 wv = g_wgt[b];
    const float* b2a = b2 + ((size_t)blk * EE + se.x) * DD;
    const float* b2b = b2 + ((size_t)blk * EE + se.y) * DD;
    const float* e0 = g_Eout + (size_t)(2 * b) * DD;
    const float* e1 = e0 + DD;

    float v[4];
    float s = 0.f;
    #pragma unroll
    for (int i = 0; i < 4; i++) {
        int n = tid + 256 * i;
        v[i] = xrow[n] + wv.x * b2a[n] + wv.y * b2b[n] + e0[n] + e1[n];
        s += v[i];
    }
    float tot = blockReduceSum(s, red);
    if (tid == 0) bc[0] = tot;
    __syncthreads();
    float mu = bc[0] * (1.f / 1024.f);

    float s2 = 0.f;
    #pragma unroll
    for (int i = 0; i < 4; i++) { float d = v[i] - mu; s2 += d * d; }
    float tot2 = blockReduceSum(s2, red);
    if (tid == 0) bc[1] = tot2;
    __syncthreads();
    float inv = 1.f / sqrtf(bc[1] * (1.f / 1024.f) + 1e-5f);

    #pragma unroll
    for (int i = 0; i < 4; i++) {
        int n = tid + 256 * i;
        Y[(size_t)b * DD + n] = (v[i] - mu) * inv * gam[blk * DD + n] + bet[blk * DD + n];
    }
}

// ---------------- launch ----------------
extern "C" void kernel_launch(void* const* d_in, const int* in_sizes, int n_in,
                              void* d_out, int out_size)
{
    (void)in_sizes; (void)n_in; (void)out_size;
    const float* x  = (const float*)d_in[0];
    const float* gW = (const float*)d_in[1];
    const float* gb = (const float*)d_in[2];
    const float* qp = (const float*)d_in[3];
    const float* rW = (const float*)d_in[4];
    const float* rb = (const float*)d_in[5];
    const float* w2 = (const float*)d_in[6];
    const float* b2 = (const float*)d_in[7];
    const float* lg = (const float*)d_in[8];
    const float* lb = (const float*)d_in[9];
    float* out = (float*)d_out;

    cudaFuncSetAttribute(k_moe_gemm_mma, cudaFuncAttributeMaxDynamicSharedMemorySize, GEMM_SMEM);

    // one-time per launch: transposes + fp16-convert w2 (+ reset cnt)
    k_gwt<<<(2 * DD * EE + 255) / 256, 256>>>(gW);
    k_w2t<<<dim3(DD / 32, HHv / 32, 2 * EE), 256>>>(w2);

    for (int blk = 0; blk < 2; blk++) {
        k_gate_qsim_w<<<BB / 8, 256>>>(x, gb, qp, blk);
        k_hidden<<<dim3(EE, (2 * BB) / HSLOTS), 256>>>(rW, rb, blk);
        dim3 g2(DD / BN, BB / BM, EE);
        k_moe_gemm_mma<<<g2, 256, GEMM_SMEM>>>(blk);
        k_ln<<<BB, 256>>>(x, b2, lg, lb, out, blk);
    }
}